// round 4
// baseline (speedup 1.0000x reference)
#include <cuda_runtime.h>
#include <math.h>

#define Bn 64
#define Tn 512
#define Cn 384
#define Hn 6
#define HDn 64
#define FFn 1536
#define BTn (Bn*Tn)
#define EPSn 1e-5f
#define SMS 136   // gemm smem row stride (u32)

// attention smem strides (u32)
#define STQ 68
#define STK 68
#define STV 36
#define STP 36

// ---------------- scratch ----------------
__device__ float g_wqkv[Cn*3*Cn];
__device__ float g_bqkv[3*Cn];
__device__ float g_q[(size_t)Bn*Hn*Tn*HDn];
__device__ float g_k[(size_t)Bn*Hn*Tn*HDn];
__device__ float g_v[(size_t)Bn*Hn*Tn*HDn];
__device__ float g_o[(size_t)BTn*Cn];
__device__ float g_p[(size_t)BTn*Cn];
__device__ float g_r1[(size_t)BTn*Cn];
__device__ float g_r2[(size_t)BTn*Cn];
__device__ float g_h[(size_t)BTn*FFn];

// ---------------- packs ----------------
__global__ void qkv_pack_w(const float* __restrict__ qw, const float* __restrict__ kw,
                           const float* __restrict__ vw, float* __restrict__ o) {
    int idx = blockIdx.x * blockDim.x + threadIdx.x;
    if (idx >= Cn * 3 * Cn) return;
    int c = idx / (3 * Cn);
    int col = idx % (3 * Cn);
    int mat = col / Cn;
    int local = col % Cn;
    int h = local >> 6, d = local & 63;
    const float* w = (mat == 0) ? qw : (mat == 1) ? kw : vw;
    o[idx] = w[((size_t)h * Cn + c) * HDn + d];
}
__global__ void qkv_pack_b(const float* __restrict__ qb, const float* __restrict__ kb,
                           const float* __restrict__ vb, float* __restrict__ o) {
    int i = threadIdx.x + blockIdx.x * blockDim.x;
    if (i >= 3 * Cn) return;
    const float* b = (i < Cn) ? qb : (i < 2 * Cn) ? kb : vb;
    o[i] = b[i % Cn];
}

// ---------------- tf32 helpers ----------------
__device__ __forceinline__ unsigned f2tf(float x) {
    unsigned r; asm("cvt.rna.tf32.f32 %0, %1;" : "=r"(r) : "f"(x)); return r;
}
__device__ __forceinline__ void mma8(float* d, const unsigned* a, const unsigned* b) {
    asm("mma.sync.aligned.m16n8k8.row.col.f32.tf32.tf32.f32 "
        "{%0,%1,%2,%3},{%4,%5,%6,%7},{%8,%9},{%0,%1,%2,%3};"
        : "+f"(d[0]), "+f"(d[1]), "+f"(d[2]), "+f"(d[3])
        : "r"(a[0]), "r"(a[1]), "r"(a[2]), "r"(a[3]), "r"(b[0]), "r"(b[1]));
}

// ---------------- tf32 GEMM v2: 128x128 block, 4 warps (2x2), warp 64x64 --------
// smem holds PRE-CONVERTED tf32; inner loop is pure LDS + MMA.
// flags: bit0 relu; bit1 qkv-scatter (+rope on q/k)
__global__ __launch_bounds__(128) void gemm_tf32(
    const float* __restrict__ A, const float* __restrict__ Bm,
    const float* __restrict__ bias, float* __restrict__ Cout,
    int M, int N, int K, int flags,
    float* __restrict__ oq, float* __restrict__ ok, float* __restrict__ ov)
{
    __shared__ unsigned As[2][16 * SMS];
    __shared__ unsigned Bs[2][16 * SMS];

    const int tid = threadIdx.x;
    const int lane = tid & 31, warp = tid >> 5;
    const int warpM = warp >> 1, warpN = warp & 1;    // 2 x 2
    const int bm = blockIdx.y * 128, bn = blockIdx.x * 128;
    const int qq = lane & 3, gg = lane >> 2;

    // global mappings: A one row/thread (16 k), B 16 rows x 128 cols
    const int bRow = tid >> 3, bCol = (tid & 7) * 4;
    const float* Ap = A + (size_t)(bm + tid) * K;
    const float* Bp = Bm + (size_t)bRow * N + bn + bCol;

    float acc[4][8][4];
#pragma unroll
    for (int i = 0; i < 4; i++)
#pragma unroll
        for (int j = 0; j < 8; j++)
#pragma unroll
            for (int r = 0; r < 4; r++) acc[i][j][r] = 0.f;

    float4 ra[4], rb[4];
    // preload kt=0
#pragma unroll
    for (int u = 0; u < 4; u++) ra[u] = *(const float4*)(Ap + u * 4);
#pragma unroll
    for (int c = 0; c < 4; c++) rb[c] = *(const float4*)(Bp + c * 32);
    {
        unsigned* as = As[0]; unsigned* bs = Bs[0];
#pragma unroll
        for (int u = 0; u < 4; u++) {
            as[(u * 4 + 0) * SMS + tid] = f2tf(ra[u].x);
            as[(u * 4 + 1) * SMS + tid] = f2tf(ra[u].y);
            as[(u * 4 + 2) * SMS + tid] = f2tf(ra[u].z);
            as[(u * 4 + 3) * SMS + tid] = f2tf(ra[u].w);
        }
#pragma unroll
        for (int c = 0; c < 4; c++) {
            uint4 u4 = make_uint4(f2tf(rb[c].x), f2tf(rb[c].y), f2tf(rb[c].z), f2tf(rb[c].w));
            *(uint4*)(&bs[bRow * SMS + bCol + c * 32]) = u4;
        }
    }
    __syncthreads();

    const int KT = K >> 4;
    for (int kt = 0; kt < KT; kt++) {
        if (kt + 1 < KT) {
            const float* ap = Ap + (kt + 1) * 16;
            const float* bp = Bp + (size_t)(kt + 1) * 16 * N;
#pragma unroll
            for (int u = 0; u < 4; u++) ra[u] = *(const float4*)(ap + u * 4);
#pragma unroll
            for (int c = 0; c < 4; c++) rb[c] = *(const float4*)(bp + c * 32);
        }
        const unsigned* as = As[kt & 1];
        const unsigned* bs = Bs[kt & 1];
#pragma unroll
        for (int kk = 0; kk < 16; kk += 8) {
            unsigned af[4][4], bf[8][2];
#pragma unroll
            for (int mi = 0; mi < 4; mi++) {
                int m0 = warpM * 64 + mi * 16 + gg;
                af[mi][0] = as[(kk + qq) * SMS + m0];
                af[mi][1] = as[(kk + qq) * SMS + m0 + 8];
                af[mi][2] = as[(kk + qq + 4) * SMS + m0];
                af[mi][3] = as[(kk + qq + 4) * SMS + m0 + 8];
            }
#pragma unroll
            for (int ni = 0; ni < 8; ni++) {
                int n0 = warpN * 64 + ni * 8 + gg;
                bf[ni][0] = bs[(kk + qq) * SMS + n0];
                bf[ni][1] = bs[(kk + qq + 4) * SMS + n0];
            }
#pragma unroll
            for (int mi = 0; mi < 4; mi++)
#pragma unroll
                for (int ni = 0; ni < 8; ni++)
                    mma8(acc[mi][ni], af[mi], bf[ni]);
        }
        if (kt + 1 < KT) {
            unsigned* asw = As[(kt + 1) & 1]; unsigned* bsw = Bs[(kt + 1) & 1];
#pragma unroll
            for (int u = 0; u < 4; u++) {
                asw[(u * 4 + 0) * SMS + tid] = f2tf(ra[u].x);
                asw[(u * 4 + 1) * SMS + tid] = f2tf(ra[u].y);
                asw[(u * 4 + 2) * SMS + tid] = f2tf(ra[u].z);
                asw[(u * 4 + 3) * SMS + tid] = f2tf(ra[u].w);
            }
#pragma unroll
            for (int c = 0; c < 4; c++) {
                uint4 u4 = make_uint4(f2tf(rb[c].x), f2tf(rb[c].y), f2tf(rb[c].z), f2tf(rb[c].w));
                *(uint4*)(&bsw[bRow * SMS + bCol + c * 32]) = u4;
            }
            __syncthreads();
        }
    }

    // -------- epilogue --------
    const bool relu = (flags & 1) != 0;
    const bool qkv = (flags & 2) != 0;

#pragma unroll
    for (int mi = 0; mi < 4; mi++) {
        int row0 = bm + warpM * 64 + mi * 16 + gg;
        float sn[2], cs[2];
        if (qkv) {
            sincosf((float)(row0 & 511), &sn[0], &cs[0]);
            sincosf((float)((row0 + 8) & 511), &sn[1], &cs[1]);
        }
#pragma unroll
        for (int ni = 0; ni < 8; ni++) {
            int col = bn + warpN * 64 + ni * 8 + qq * 2;
            float b0 = bias[col], b1 = bias[col + 1];
#pragma unroll
            for (int half = 0; half < 2; half++) {
                int row = row0 + half * 8;
                float xr = acc[mi][ni][half * 2 + 0] + b0;
                float xi = acc[mi][ni][half * 2 + 1] + b1;
                if (qkv) {
                    int mat = col / Cn;
                    if (mat < 2) {
                        float nr = cs[half] * xr - sn[half] * xi;
                        float ni2 = sn[half] * xr + cs[half] * xi;
                        xr = nr; xi = ni2;
                    }
                    int local = col - mat * Cn;
                    int h = local >> 6, d = local & 63;
                    int bb = row >> 9, t = row & 511;
                    float* dst = (mat == 0) ? oq : (mat == 1) ? ok : ov;
                    float2* p = (float2*)(dst + (((size_t)(bb * Hn + h) * Tn + t) * HDn + d));
                    *p = make_float2(xr, xi);
                } else {
                    if (relu) { xr = fmaxf(xr, 0.f); xi = fmaxf(xi, 0.f); }
                    float2* p = (float2*)(Cout + (size_t)row * N + col);
                    *p = make_float2(xr, xi);
                }
            }
        }
    }
}

// ---------------- tensor-core causal flash attention (pre-converted tf32 smem) ----
__global__ __launch_bounds__(128) void attn_mma(
    const float* __restrict__ q, const float* __restrict__ k,
    const float* __restrict__ v, float* __restrict__ o)
{
    __shared__ unsigned sm[32 * STK + 64 * STV];   // Ks | Vt (Q staging overlays: 64*STQ=4352)
    __shared__ unsigned Ps[64 * STP];
    unsigned* Ks = sm;
    unsigned* Vt = sm + 32 * STK;

    const int bh = blockIdx.y;
    const int qt = gridDim.x - 1 - blockIdx.x;   // long blocks first
    const int tid = threadIdx.x;
    const int warp = tid >> 5, lane = tid & 31;
    const int gg = lane >> 2, qq = lane & 3;
    const size_t base = (size_t)bh * Tn * HDn;
    const int q0 = qt * 64;
    const float scale = 0.051031036307982884f;   // 1/sqrt(384)

    // stage scaled Q (fp32 bits) into sm
    for (int i = tid; i < 64 * 16; i += 128) {
        int r = i >> 4, d4 = (i & 15) * 4;
        float4 t4 = *(const float4*)(q + base + (size_t)(q0 + r) * 64 + d4);
        uint4 u4 = make_uint4(__float_as_uint(t4.x * scale), __float_as_uint(t4.y * scale),
                              __float_as_uint(t4.z * scale), __float_as_uint(t4.w * scale));
        *(uint4*)(sm + r * STQ + d4) = u4;
    }
    __syncthreads();

    // Q A-fragments (tf32)
    unsigned qf[8][4];
    {
        const unsigned* qr = sm + (warp * 16 + gg) * STQ;
#pragma unroll
        for (int ks = 0; ks < 8; ks++) {
            qf[ks][0] = f2tf(__uint_as_float(qr[ks * 8 + qq]));
            qf[ks][1] = f2tf(__uint_as_float(qr[8 * STQ + ks * 8 + qq]));
            qf[ks][2] = f2tf(__uint_as_float(qr[ks * 8 + qq + 4]));
            qf[ks][3] = f2tf(__uint_as_float(qr[8 * STQ + ks * 8 + qq + 4]));
        }
    }
    __syncthreads();

    float oacc[8][4];
#pragma unroll
    for (int i = 0; i < 8; i++)
#pragma unroll
        for (int r = 0; r < 4; r++) oacc[i][r] = 0.f;
    float m0 = -INFINITY, m1 = -INFINITY, l0 = 0.f, l1 = 0.f;

    const int row0g = q0 + warp * 16 + gg;
    const int row1g = row0g + 8;
    const int ktiles = 2 * qt + 2;

    for (int kt = 0; kt < ktiles; kt++) {
        const int kbase = kt * 32;
        // K tile [32][64] tf32; V tile transposed [64][32] tf32
        for (int i = tid; i < 32 * 16; i += 128) {
            int r = i >> 4, d4 = (i & 15) * 4;
            float4 t4 = *(const float4*)(k + base + (size_t)(kbase + r) * 64 + d4);
            uint4 u4k = make_uint4(f2tf(t4.x), f2tf(t4.y), f2tf(t4.z), f2tf(t4.w));
            *(uint4*)(Ks + r * STK + d4) = u4k;
            float4 u4 = *(const float4*)(v + base + (size_t)(kbase + r) * 64 + d4);
            Vt[(d4 + 0) * STV + r] = f2tf(u4.x);
            Vt[(d4 + 1) * STV + r] = f2tf(u4.y);
            Vt[(d4 + 2) * STV + r] = f2tf(u4.z);
            Vt[(d4 + 3) * STV + r] = f2tf(u4.w);
        }
        __syncthreads();

        // S = Q K^T
        float s[4][4];
#pragma unroll
        for (int nt = 0; nt < 4; nt++)
#pragma unroll
            for (int r = 0; r < 4; r++) s[nt][r] = 0.f;
#pragma unroll
        for (int ks = 0; ks < 8; ks++) {
            unsigned bf[4][2];
#pragma unroll
            for (int nt = 0; nt < 4; nt++) {
                bf[nt][0] = Ks[(nt * 8 + gg) * STK + ks * 8 + qq];
                bf[nt][1] = Ks[(nt * 8 + gg) * STK + ks * 8 + qq + 4];
            }
#pragma unroll
            for (int nt = 0; nt < 4; nt++) mma8(s[nt], qf[ks], bf[nt]);
        }

        // causal mask (diagonal 64-key block only)
        if (kt >= 2 * qt) {
#pragma unroll
            for (int nt = 0; nt < 4; nt++) {
                int c0 = kbase + nt * 8 + 2 * qq;
                if (c0 > row0g)     s[nt][0] = -1e30f;
                if (c0 + 1 > row0g) s[nt][1] = -1e30f;
                if (c0 > row1g)     s[nt][2] = -1e30f;
                if (c0 + 1 > row1g) s[nt][3] = -1e30f;
            }
        }

        // online softmax
        float rm0 = -1e30f, rm1 = -1e30f;
#pragma unroll
        for (int nt = 0; nt < 4; nt++) {
            rm0 = fmaxf(rm0, fmaxf(s[nt][0], s[nt][1]));
            rm1 = fmaxf(rm1, fmaxf(s[nt][2], s[nt][3]));
        }
        rm0 = fmaxf(rm0, __shfl_xor_sync(0xffffffffu, rm0, 1));
        rm0 = fmaxf(rm0, __shfl_xor_sync(0xffffffffu, rm0, 2));
        rm1 = fmaxf(rm1, __shfl_xor_sync(0xffffffffu, rm1, 1));
        rm1 = fmaxf(rm1, __shfl_xor_sync(0xffffffffu, rm1, 2));
        float nm0 = fmaxf(m0, rm0), nm1 = fmaxf(m1, rm1);
        float corr0 = __expf(m0 - nm0), corr1 = __expf(m1 - nm1);
        float rs0 = 0.f, rs1 = 0.f;
#pragma unroll
        for (int nt = 0; nt < 4; nt++) {
            s[nt][0] = __expf(s[nt][0] - nm0);
            s[nt][1] = __expf(s[nt][1] - nm0);
            s[nt][2] = __expf(s[nt][2] - nm1);
            s[nt][3] = __expf(s[nt][3] - nm1);
            rs0 += s[nt][0] + s[nt][1];
            rs1 += s[nt][2] + s[nt][3];
        }
        rs0 += __shfl_xor_sync(0xffffffffu, rs0, 1);
        rs0 += __shfl_xor_sync(0xffffffffu, rs0, 2);
        rs1 += __shfl_xor_sync(0xffffffffu, rs1, 1);
        rs1 += __shfl_xor_sync(0xffffffffu, rs1, 2);
        l0 = l0 * corr0 + rs0;
        l1 = l1 * corr1 + rs1;
        m0 = nm0; m1 = nm1;
#pragma unroll
        for (int nt = 0; nt < 8; nt++) {
            oacc[nt][0] *= corr0; oacc[nt][1] *= corr0;
            oacc[nt][2] *= corr1; oacc[nt][3] *= corr1;
        }

        // stage P as tf32 (warp-private rows)
        {
            unsigned* pr = Ps + (warp * 16 + gg) * STP;
#pragma unroll
            for (int nt = 0; nt < 4; nt++) {
                *(uint2*)(pr + nt * 8 + 2 * qq) = make_uint2(f2tf(s[nt][0]), f2tf(s[nt][1]));
                *(uint2*)(pr + 8 * STP + nt * 8 + 2 * qq) = make_uint2(f2tf(s[nt][2]), f2tf(s[nt][3]));
            }
        }
        __syncwarp();

        // O += P V
#pragma unroll
        for (int ks = 0; ks < 4; ks++) {
            unsigned af[4];
            const unsigned* pr = Ps + (warp * 16 + gg) * STP + ks * 8;
            af[0] = pr[qq];
            af[1] = pr[8 * STP + qq];
            af[2] = pr[qq + 4];
            af[3] = pr[8 * STP + qq + 4];
#pragma unroll
            for (int nt = 0; nt < 8; nt++) {
                unsigned bf2[2];
                bf2[0] = Vt[(nt * 8 + gg) * STV + ks * 8 + qq];
                bf2[1] = Vt[(nt * 8 + gg) * STV + ks * 8 + qq + 4];
                mma8(oacc[nt], af, bf2);
            }
        }
        __syncthreads();
    }

    // epilogue: normalize, scatter to [BT, C]
    const float inv0 = 1.f / l0, inv1 = 1.f / l1;
    const int b = bh / Hn, h = bh % Hn;
    float* p0 = o + ((size_t)(b * Tn + row0g)) * Cn + h * 64;
    float* p1 = o + ((size_t)(b * Tn + row1g)) * Cn + h * 64;
#pragma unroll
    for (int nt = 0; nt < 8; nt++) {
        *(float2*)(p0 + nt * 8 + 2 * qq) = make_float2(oacc[nt][0] * inv0, oacc[nt][1] * inv0);
        *(float2*)(p1 + nt * 8 + 2 * qq) = make_float2(oacc[nt][2] * inv1, oacc[nt][3] * inv1);
    }
}

// ---------------- fused residual + LayerNorm ----------------
__global__ __launch_bounds__(128) void ln_res_k(
    const float* __restrict__ x, const float* __restrict__ y,
    const float* __restrict__ g, const float* __restrict__ bb,
    float* __restrict__ out)
{
    __shared__ float red[4];
    const int row = blockIdx.x;
    const int tid = threadIdx.x;
    const size_t base = (size_t)row * Cn;
    float v0 = x[base + tid]       + y[base + tid];
    float v1 = x[base + tid + 128] + y[base + tid + 128];
    float v2 = x[base + tid + 256] + y[base + tid + 256];

    float s = v0 + v1 + v2;
    for (int o = 16; o > 0; o >>= 1) s += __shfl_xor_sync(0xffffffffu, s, o);
    if ((tid & 31) == 0) red[tid >> 5] = s;
    __syncthreads();
    float mean = (red[0] + red[1] + red[2] + red[3]) * (1.f / Cn);
    __syncthreads();

    float d0 = v0 - mean, d1 = v1 - mean, d2 = v2 - mean;
    float sq = d0 * d0 + d1 * d1 + d2 * d2;
    for (int o = 16; o > 0; o >>= 1) sq += __shfl_xor_sync(0xffffffffu, sq, o);
    if ((tid & 31) == 0) red[tid >> 5] = sq;
    __syncthreads();
    float var = (red[0] + red[1] + red[2] + red[3]) * (1.f / Cn);
    float inv = rsqrtf(var + EPSn);

    out[base + tid]       = g[tid]       * d0 * inv + bb[tid];
    out[base + tid + 128] = g[tid + 128] * d1 * inv + bb[tid + 128];
    out[base + tid + 256] = g[tid + 256] * d2 * inv + bb[tid + 256];
}

// ---------------- host orchestration ----------------
extern "C" void kernel_launch(void* const* d_in, const int* in_sizes, int n_in,
                              void* d_out, int out_size)
{
    (void)in_sizes; (void)n_in; (void)out_size;
    const float* x    = (const float*)d_in[0];
    const float* q1w  = (const float*)d_in[1];
    const float* q1b  = (const float*)d_in[2];
    const float* k1w  = (const float*)d_in[3];
    const float* k1b  = (const float*)d_in[4];
    const float* v1w  = (const float*)d_in[5];
    const float* v1b  = (const float*)d_in[6];
    const float* p1w  = (const float*)d_in[7];
    const float* p1b  = (const float*)d_in[8];
    const float* ln1g = (const float*)d_in[9];
    const float* ln1b = (const float*)d_in[10];
    const float* q2w  = (const float*)d_in[11];
    const float* q2b  = (const float*)d_in[12];
    const float* k2w  = (const float*)d_in[13];
    const float* k2b  = (const float*)d_in[14];
    const float* v2w  = (const float*)d_in[15];
    const float* v2b  = (const float*)d_in[16];
    const float* p2w  = (const float*)d_in[17];
    const float* p2b  = (const float*)d_in[18];
    const float* ln2g = (const float*)d_in[19];
    const float* ln2b = (const float*)d_in[20];
    const float* f1w  = (const float*)d_in[21];
    const float* f1b  = (const float*)d_in[22];
    const float* f2w  = (const float*)d_in[23];
    const float* f2b  = (const float*)d_in[24];
    const float* ln3g = (const float*)d_in[25];
    const float* ln3b = (const float*)d_in[26];
    float* out = (float*)d_out;

    float *pwqkv, *pbqkv, *pq, *pk, *pv, *po, *pp, *pr1, *pr2, *ph;
    cudaGetSymbolAddress((void**)&pwqkv, g_wqkv);
    cudaGetSymbolAddress((void**)&pbqkv, g_bqkv);
    cudaGetSymbolAddress((void**)&pq,  g_q);
    cudaGetSymbolAddress((void**)&pk,  g_k);
    cudaGetSymbolAddress((void**)&pv,  g_v);
    cudaGetSymbolAddress((void**)&po,  g_o);
    cudaGetSymbolAddress((void**)&pp,  g_p);
    cudaGetSymbolAddress((void**)&pr1, g_r1);
    cudaGetSymbolAddress((void**)&pr2, g_r2);
    cudaGetSymbolAddress((void**)&ph,  g_h);

    const int nPack = Cn * 3 * Cn;

    auto run_layer = [&](const float* xin,
                         const float* qw, const float* qb,
                         const float* kw, const float* kb,
                         const float* vw, const float* vb,
                         const float* pw, const float* pb,
                         const float* lng, const float* lnb,
                         float* rout) {
        qkv_pack_w<<<(nPack + 255) / 256, 256>>>(qw, kw, vw, pwqkv);
        qkv_pack_b<<<(3 * Cn + 255) / 256, 256>>>(qb, kb, vb, pbqkv);
        gemm_tf32<<<dim3(3 * Cn / 128, BTn / 128), 128>>>(
            xin, pwqkv, pbqkv, nullptr, BTn, 3 * Cn, Cn, 2, pq, pk, pv);
        attn_mma<<<dim3(Tn / 64, Bn * Hn), 128>>>(pq, pk, pv, po);
        gemm_tf32<<<dim3(Cn / 128, BTn / 128), 128>>>(
            po, pw, pb, pp, BTn, Cn, Cn, 0, nullptr, nullptr, nullptr);
        ln_res_k<<<BTn, 128>>>(xin, pp, lng, lnb, rout);
    };

    run_layer(x,   q1w, q1b, k1w, k1b, v1w, v1b, p1w, p1b, ln1g, ln1b, pr1);
    run_layer(pr1, q2w, q2b, k2w, k2b, v2w, v2b, p2w, p2b, ln2g, ln2b, pr2);

    gemm_tf32<<<dim3(FFn / 128, BTn / 128), 128>>>(
        pr2, f1w, f1b, ph, BTn, FFn, Cn, 1, nullptr, nullptr, nullptr);
    gemm_tf32<<<dim3(Cn / 128, BTn / 128), 128>>>(
        ph, f2w, f2b, pp, BTn, Cn, FFn, 0, nullptr, nullptr, nullptr);
    ln_res_k<<<BTn, 128>>>(pr2, pp, ln3g, ln3b, out);
}

// round 5
// speedup vs baseline: 1.1872x; 1.1872x over previous
#include <cuda_runtime.h>
#include <math.h>

#define Bn 64
#define Tn 512
#define Cn 384
#define Hn 6
#define HDn 64
#define FFn 1536
#define BTn (Bn*Tn)
#define EPSn 1e-5f
#define SMS 136   // gemm smem row stride (u32)

// attention smem strides (u32)
#define STQ 68
#define STK 68
#define STV 72    // 72 % 32 == 8 -> conflict-free row-major V B-fragment reads
#define STP 36

// attention smem layout (u32 offsets)
#define AKS0 0
#define AVS0 (32*STK)
#define AKS1 (AVS0 + 32*STV)
#define AVS1 (AKS1 + 32*STK)
#define APS  (AVS1 + 32*STV)
#define ASMT (APS + 64*STP)

// ---------------- scratch ----------------
__device__ float g_wqkv[Cn*3*Cn];
__device__ float g_bqkv[3*Cn];
__device__ float g_q[(size_t)Bn*Hn*Tn*HDn];
__device__ float g_k[(size_t)Bn*Hn*Tn*HDn];
__device__ float g_v[(size_t)Bn*Hn*Tn*HDn];
__device__ float g_o[(size_t)BTn*Cn];
__device__ float g_p[(size_t)BTn*Cn];
__device__ float g_r1[(size_t)BTn*Cn];
__device__ float g_r2[(size_t)BTn*Cn];
__device__ float g_h[(size_t)BTn*FFn];

// ---------------- packs ----------------
__global__ void qkv_pack_w(const float* __restrict__ qw, const float* __restrict__ kw,
                           const float* __restrict__ vw, float* __restrict__ o) {
    int idx = blockIdx.x * blockDim.x + threadIdx.x;
    if (idx >= Cn * 3 * Cn) return;
    int c = idx / (3 * Cn);
    int col = idx % (3 * Cn);
    int mat = col / Cn;
    int local = col % Cn;
    int h = local >> 6, d = local & 63;
    const float* w = (mat == 0) ? qw : (mat == 1) ? kw : vw;
    o[idx] = w[((size_t)h * Cn + c) * HDn + d];
}
__global__ void qkv_pack_b(const float* __restrict__ qb, const float* __restrict__ kb,
                           const float* __restrict__ vb, float* __restrict__ o) {
    int i = threadIdx.x + blockIdx.x * blockDim.x;
    if (i >= 3 * Cn) return;
    const float* b = (i < Cn) ? qb : (i < 2 * Cn) ? kb : vb;
    o[i] = b[i % Cn];
}

// ---------------- tf32 / async helpers ----------------
__device__ __forceinline__ unsigned f2tf(float x) {
    unsigned r; asm("cvt.rna.tf32.f32 %0, %1;" : "=r"(r) : "f"(x)); return r;
}
__device__ __forceinline__ void mma8(float* d, const unsigned* a, const unsigned* b) {
    asm("mma.sync.aligned.m16n8k8.row.col.f32.tf32.tf32.f32 "
        "{%0,%1,%2,%3},{%4,%5,%6,%7},{%8,%9},{%0,%1,%2,%3};"
        : "+f"(d[0]), "+f"(d[1]), "+f"(d[2]), "+f"(d[3])
        : "r"(a[0]), "r"(a[1]), "r"(a[2]), "r"(a[3]), "r"(b[0]), "r"(b[1]));
}
__device__ __forceinline__ void cp_async16(void* smem_dst, const void* gsrc) {
    unsigned saddr = (unsigned)__cvta_generic_to_shared(smem_dst);
    asm volatile("cp.async.ca.shared.global [%0], [%1], 16;\n" :: "r"(saddr), "l"(gsrc));
}
#define CP_COMMIT() asm volatile("cp.async.commit_group;\n" ::: "memory")
#define CP_WAIT0()  asm volatile("cp.async.wait_group 0;\n" ::: "memory")

// ---------------- tf32 GEMM: R3 shape (256 thr, warps 2x4, warp 64x32),
//                  smem PRE-CONVERTED tf32; inner loop pure LDS+MMA --------------
// flags: bit0 relu; bit1 qkv-scatter (+rope on q/k)
__global__ __launch_bounds__(256) void gemm_tf32(
    const float* __restrict__ A, const float* __restrict__ Bm,
    const float* __restrict__ bias, float* __restrict__ Cout,
    int M, int N, int K, int flags,
    float* __restrict__ oq, float* __restrict__ ok, float* __restrict__ ov)
{
    __shared__ unsigned As[2][16 * SMS];
    __shared__ unsigned Bs[2][16 * SMS];

    const int tid = threadIdx.x;
    const int lane = tid & 31, warp = tid >> 5;
    const int warpM = warp >> 2, warpN = warp & 3;   // 2 x 4
    const int bm = blockIdx.y * 128, bn = blockIdx.x * 128;
    const int qq = lane & 3, gg = lane >> 2;

    const int aRow = tid >> 1;
    const int aK = (tid & 1) * 8;
    const int bK = tid >> 4;
    const int bN4 = (tid & 15) * 4;
    const float* Ap = A + (size_t)(bm + aRow) * K + aK;
    const float* Bp = Bm + (size_t)bK * N + bn + bN4;

    float acc[4][4][4];
#pragma unroll
    for (int i = 0; i < 4; i++)
#pragma unroll
        for (int j = 0; j < 4; j++)
#pragma unroll
            for (int r = 0; r < 4; r++) acc[i][j][r] = 0.f;

    float4 sa0, sa1, sb0, sb1;
    sa0 = *(const float4*)(Ap);
    sa1 = *(const float4*)(Ap + 4);
    sb0 = *(const float4*)(Bp);
    sb1 = *(const float4*)(Bp + 64);
    {
        unsigned* as = As[0]; unsigned* bs = Bs[0];
        as[(aK + 0) * SMS + aRow] = f2tf(sa0.x); as[(aK + 1) * SMS + aRow] = f2tf(sa0.y);
        as[(aK + 2) * SMS + aRow] = f2tf(sa0.z); as[(aK + 3) * SMS + aRow] = f2tf(sa0.w);
        as[(aK + 4) * SMS + aRow] = f2tf(sa1.x); as[(aK + 5) * SMS + aRow] = f2tf(sa1.y);
        as[(aK + 6) * SMS + aRow] = f2tf(sa1.z); as[(aK + 7) * SMS + aRow] = f2tf(sa1.w);
        *(uint4*)(&bs[bK * SMS + bN4]) = make_uint4(f2tf(sb0.x), f2tf(sb0.y), f2tf(sb0.z), f2tf(sb0.w));
        *(uint4*)(&bs[bK * SMS + bN4 + 64]) = make_uint4(f2tf(sb1.x), f2tf(sb1.y), f2tf(sb1.z), f2tf(sb1.w));
    }
    __syncthreads();

    const int KT = K >> 4;
    for (int kt = 0; kt < KT; kt++) {
        if (kt + 1 < KT) {
            const float* ap = Ap + (size_t)(kt + 1) * 16;
            const float* bp = Bp + (size_t)(kt + 1) * 16 * N;
            sa0 = *(const float4*)(ap);
            sa1 = *(const float4*)(ap + 4);
            sb0 = *(const float4*)(bp);
            sb1 = *(const float4*)(bp + 64);
        }
        const unsigned* as = As[kt & 1];
        const unsigned* bs = Bs[kt & 1];
#pragma unroll
        for (int kk = 0; kk < 16; kk += 8) {
            unsigned af[4][4], bf[4][2];
#pragma unroll
            for (int mi = 0; mi < 4; mi++) {
                int m0 = warpM * 64 + mi * 16 + gg;
                af[mi][0] = as[(kk + qq) * SMS + m0];
                af[mi][1] = as[(kk + qq) * SMS + m0 + 8];
                af[mi][2] = as[(kk + qq + 4) * SMS + m0];
                af[mi][3] = as[(kk + qq + 4) * SMS + m0 + 8];
            }
#pragma unroll
            for (int ni = 0; ni < 4; ni++) {
                int n0 = warpN * 32 + ni * 8 + gg;
                bf[ni][0] = bs[(kk + qq) * SMS + n0];
                bf[ni][1] = bs[(kk + qq + 4) * SMS + n0];
            }
#pragma unroll
            for (int mi = 0; mi < 4; mi++)
#pragma unroll
                for (int ni = 0; ni < 4; ni++)
                    mma8(acc[mi][ni], af[mi], bf[ni]);
        }
        if (kt + 1 < KT) {
            unsigned* asw = As[(kt + 1) & 1]; unsigned* bsw = Bs[(kt + 1) & 1];
            asw[(aK + 0) * SMS + aRow] = f2tf(sa0.x); asw[(aK + 1) * SMS + aRow] = f2tf(sa0.y);
            asw[(aK + 2) * SMS + aRow] = f2tf(sa0.z); asw[(aK + 3) * SMS + aRow] = f2tf(sa0.w);
            asw[(aK + 4) * SMS + aRow] = f2tf(sa1.x); asw[(aK + 5) * SMS + aRow] = f2tf(sa1.y);
            asw[(aK + 6) * SMS + aRow] = f2tf(sa1.z); asw[(aK + 7) * SMS + aRow] = f2tf(sa1.w);
            *(uint4*)(&bsw[bK * SMS + bN4]) = make_uint4(f2tf(sb0.x), f2tf(sb0.y), f2tf(sb0.z), f2tf(sb0.w));
            *(uint4*)(&bsw[bK * SMS + bN4 + 64]) = make_uint4(f2tf(sb1.x), f2tf(sb1.y), f2tf(sb1.z), f2tf(sb1.w));
            __syncthreads();
        }
    }

    const bool relu = (flags & 1) != 0;
    const bool qkv = (flags & 2) != 0;

#pragma unroll
    for (int mi = 0; mi < 4; mi++) {
        int row0 = bm + warpM * 64 + mi * 16 + gg;
        float sn[2], cs[2];
        if (qkv) {
            sincosf((float)(row0 & 511), &sn[0], &cs[0]);
            sincosf((float)((row0 + 8) & 511), &sn[1], &cs[1]);
        }
#pragma unroll
        for (int ni = 0; ni < 4; ni++) {
            int col = bn + warpN * 32 + ni * 8 + qq * 2;
            float b0 = bias[col], b1 = bias[col + 1];
#pragma unroll
            for (int half = 0; half < 2; half++) {
                int row = row0 + half * 8;
                float xr = acc[mi][ni][half * 2 + 0] + b0;
                float xi = acc[mi][ni][half * 2 + 1] + b1;
                if (qkv) {
                    int mat = col / Cn;
                    if (mat < 2) {
                        float nr = cs[half] * xr - sn[half] * xi;
                        float ni2 = sn[half] * xr + cs[half] * xi;
                        xr = nr; xi = ni2;
                    }
                    int local = col - mat * Cn;
                    int h = local >> 6, d = local & 63;
                    int bb = row >> 9, t = row & 511;
                    float* dst = (mat == 0) ? oq : (mat == 1) ? ok : ov;
                    float2* p = (float2*)(dst + (((size_t)(bb * Hn + h) * Tn + t) * HDn + d));
                    *p = make_float2(xr, xi);
                } else {
                    if (relu) { xr = fmaxf(xr, 0.f); xi = fmaxf(xi, 0.f); }
                    float2* p = (float2*)(Cout + (size_t)row * N + col);
                    *p = make_float2(xr, xi);
                }
            }
        }
    }
}

// ---------------- tensor-core causal flash attention, cp.async double-buffered ----
__global__ __launch_bounds__(128) void attn_mma(
    const float* __restrict__ q, const float* __restrict__ k,
    const float* __restrict__ v, float* __restrict__ o)
{
    __shared__ unsigned sm[ASMT];
    unsigned* Ps = sm + APS;

    const int bh = blockIdx.y;
    const int qt = gridDim.x - 1 - blockIdx.x;   // long blocks first
    const int tid = threadIdx.x;
    const int warp = tid >> 5, lane = tid & 31;
    const int gg = lane >> 2, qq = lane & 3;
    const size_t base = (size_t)bh * Tn * HDn;
    const int q0 = qt * 64;
    const float scale = 0.051031036307982884f;   // 1/sqrt(384)
    const int ktiles = 2 * qt + 2;

    // prefetch KV tile 0 into buffer 0 (raw fp32 bits; mma.tf32 truncates mantissa)
    {
        unsigned* kd = sm + AKS0;
        unsigned* vd = sm + AVS0;
#pragma unroll
        for (int i = 0; i < 4; i++) {
            int idx = i * 128 + tid;
            int r = idx >> 4, c4 = (idx & 15) * 4;
            cp_async16(kd + r * STK + c4, k + base + (size_t)r * 64 + c4);
            cp_async16(vd + r * STV + c4, v + base + (size_t)r * 64 + c4);
        }
        CP_COMMIT();
    }

    // stage scaled Q into the (currently unused) buffer-1 region
    unsigned* qstage = sm + AKS1;
    for (int i = tid; i < 64 * 16; i += 128) {
        int r = i >> 4, d4 = (i & 15) * 4;
        float4 t4 = *(const float4*)(q + base + (size_t)(q0 + r) * 64 + d4);
        uint4 u4 = make_uint4(f2tf(t4.x * scale), f2tf(t4.y * scale),
                              f2tf(t4.z * scale), f2tf(t4.w * scale));
        *(uint4*)(qstage + r * STQ + d4) = u4;
    }
    __syncthreads();

    unsigned qf[8][4];
    {
        const unsigned* qr = qstage + (warp * 16 + gg) * STQ;
#pragma unroll
        for (int ks = 0; ks < 8; ks++) {
            qf[ks][0] = qr[ks * 8 + qq];
            qf[ks][1] = qr[8 * STQ + ks * 8 + qq];
            qf[ks][2] = qr[ks * 8 + qq + 4];
            qf[ks][3] = qr[8 * STQ + ks * 8 + qq + 4];
        }
    }
    __syncthreads();     // all threads done reading qstage (buffer 1 now free)
    CP_WAIT0();
    __syncthreads();     // tile 0 resident

    float oacc[8][4];
#pragma unroll
    for (int i = 0; i < 8; i++)
#pragma unroll
        for (int r = 0; r < 4; r++) oacc[i][r] = 0.f;
    float m0 = -INFINITY, m1 = -INFINITY, l0 = 0.f, l1 = 0.f;

    const int row0g = q0 + warp * 16 + gg;
    const int row1g = row0g + 8;

    for (int kt = 0; kt < ktiles; kt++) {
        const int kbase = kt * 32;
        const unsigned* Ks = sm + ((kt & 1) ? AKS1 : AKS0);
        const unsigned* Vs = sm + ((kt & 1) ? AVS1 : AVS0);

        // prefetch next tile into the other buffer (overlaps with compute below)
        if (kt + 1 < ktiles) {
            unsigned* kd = sm + (((kt + 1) & 1) ? AKS1 : AKS0);
            unsigned* vd = sm + (((kt + 1) & 1) ? AVS1 : AVS0);
            const size_t nb = base + (size_t)(kbase + 32) * 64;
#pragma unroll
            for (int i = 0; i < 4; i++) {
                int idx = i * 128 + tid;
                int r = idx >> 4, c4 = (idx & 15) * 4;
                cp_async16(kd + r * STK + c4, k + nb + (size_t)r * 64 + c4);
                cp_async16(vd + r * STV + c4, v + nb + (size_t)r * 64 + c4);
            }
            CP_COMMIT();
        }

        // S = Q K^T
        float s[4][4];
#pragma unroll
        for (int nt = 0; nt < 4; nt++)
#pragma unroll
            for (int r = 0; r < 4; r++) s[nt][r] = 0.f;
#pragma unroll
        for (int ks = 0; ks < 8; ks++) {
            unsigned bf[4][2];
#pragma unroll
            for (int nt = 0; nt < 4; nt++) {
                bf[nt][0] = Ks[(nt * 8 + gg) * STK + ks * 8 + qq];
                bf[nt][1] = Ks[(nt * 8 + gg) * STK + ks * 8 + qq + 4];
            }
#pragma unroll
            for (int nt = 0; nt < 4; nt++) mma8(s[nt], qf[ks], bf[nt]);
        }

        // causal mask (diagonal 64-key block only)
        if (kt >= 2 * qt) {
#pragma unroll
            for (int nt = 0; nt < 4; nt++) {
                int c0 = kbase + nt * 8 + 2 * qq;
                if (c0 > row0g)     s[nt][0] = -1e30f;
                if (c0 + 1 > row0g) s[nt][1] = -1e30f;
                if (c0 > row1g)     s[nt][2] = -1e30f;
                if (c0 + 1 > row1g) s[nt][3] = -1e30f;
            }
        }

        // online softmax
        float rm0 = -1e30f, rm1 = -1e30f;
#pragma unroll
        for (int nt = 0; nt < 4; nt++) {
            rm0 = fmaxf(rm0, fmaxf(s[nt][0], s[nt][1]));
            rm1 = fmaxf(rm1, fmaxf(s[nt][2], s[nt][3]));
        }
        rm0 = fmaxf(rm0, __shfl_xor_sync(0xffffffffu, rm0, 1));
        rm0 = fmaxf(rm0, __shfl_xor_sync(0xffffffffu, rm0, 2));
        rm1 = fmaxf(rm1, __shfl_xor_sync(0xffffffffu, rm1, 1));
        rm1 = fmaxf(rm1, __shfl_xor_sync(0xffffffffu, rm1, 2));
        float nm0 = fmaxf(m0, rm0), nm1 = fmaxf(m1, rm1);
        float corr0 = __expf(m0 - nm0), corr1 = __expf(m1 - nm1);
        float rs0 = 0.f, rs1 = 0.f;
#pragma unroll
        for (int nt = 0; nt < 4; nt++) {
            s[nt][0] = __expf(s[nt][0] - nm0);
            s[nt][1] = __expf(s[nt][1] - nm0);
            s[nt][2] = __expf(s[nt][2] - nm1);
            s[nt][3] = __expf(s[nt][3] - nm1);
            rs0 += s[nt][0] + s[nt][1];
            rs1 += s[nt][2] + s[nt][3];
        }
        rs0 += __shfl_xor_sync(0xffffffffu, rs0, 1);
        rs0 += __shfl_xor_sync(0xffffffffu, rs0, 2);
        rs1 += __shfl_xor_sync(0xffffffffu, rs1, 1);
        rs1 += __shfl_xor_sync(0xffffffffu, rs1, 2);
        l0 = l0 * corr0 + rs0;
        l1 = l1 * corr1 + rs1;
        m0 = nm0; m1 = nm1;
#pragma unroll
        for (int nt = 0; nt < 8; nt++) {
            oacc[nt][0] *= corr0; oacc[nt][1] *= corr0;
            oacc[nt][2] *= corr1; oacc[nt][3] *= corr1;
        }

        // stage P as tf32 (warp-private rows)
        {
            unsigned* pr = Ps + (warp * 16 + gg) * STP;
#pragma unroll
            for (int nt = 0; nt < 4; nt++) {
                *(uint2*)(pr + nt * 8 + 2 * qq) = make_uint2(f2tf(s[nt][0]), f2tf(s[nt][1]));
                *(uint2*)(pr + 8 * STP + nt * 8 + 2 * qq) = make_uint2(f2tf(s[nt][2]), f2tf(s[nt][3]));
            }
        }
        __syncwarp();

        // O += P V   (V row-major [key][d], stride 72 -> conflict-free)
#pragma unroll
        for (int ks = 0; ks < 4; ks++) {
            unsigned af[4];
            const unsigned* pr = Ps + (warp * 16 + gg) * STP + ks * 8;
            af[0] = pr[qq];
            af[1] = pr[8 * STP + qq];
            af[2] = pr[qq + 4];
            af[3] = pr[8 * STP + qq + 4];
#pragma unroll
            for (int nt = 0; nt < 8; nt++) {
                unsigned bf2[2];
                bf2[0] = Vs[(ks * 8 + qq) * STV + nt * 8 + gg];
                bf2[1] = Vs[(ks * 8 + qq + 4) * STV + nt * 8 + gg];
                mma8(oacc[nt], af, bf2);
            }
        }

        if (kt + 1 < ktiles) {
            CP_WAIT0();
            __syncthreads();
        }
    }

    // epilogue: normalize, scatter to [BT, C]
    const float inv0 = 1.f / l0, inv1 = 1.f / l1;
    const int b = bh / Hn, h = bh % Hn;
    float* p0 = o + ((size_t)(b * Tn + row0g)) * Cn + h * 64;
    float* p1 = o + ((size_t)(b * Tn + row1g)) * Cn + h * 64;
#pragma unroll
    for (int nt = 0; nt < 8; nt++) {
        *(float2*)(p0 + nt * 8 + 2 * qq) = make_float2(oacc[nt][0] * inv0, oacc[nt][1] * inv0);
        *(float2*)(p1 + nt * 8 + 2 * qq) = make_float2(oacc[nt][2] * inv1, oacc[nt][3] * inv1);
    }
}

// ---------------- fused residual + LayerNorm ----------------
__global__ __launch_bounds__(128) void ln_res_k(
    const float* __restrict__ x, const float* __restrict__ y,
    const float* __restrict__ g, const float* __restrict__ bb,
    float* __restrict__ out)
{
    __shared__ float red[4];
    const int row = blockIdx.x;
    const int tid = threadIdx.x;
    const size_t base = (size_t)row * Cn;
    float v0 = x[base + tid]       + y[base + tid];
    float v1 = x[base + tid + 128] + y[base + tid + 128];
    float v2 = x[base + tid + 256] + y[base + tid + 256];

    float s = v0 + v1 + v2;
    for (int o = 16; o > 0; o >>= 1) s += __shfl_xor_sync(0xffffffffu, s, o);
    if ((tid & 31) == 0) red[tid >> 5] = s;
    __syncthreads();
    float mean = (red[0] + red[1] + red[2] + red[3]) * (1.f / Cn);
    __syncthreads();

    float d0 = v0 - mean, d1 = v1 - mean, d2 = v2 - mean;
    float sq = d0 * d0 + d1 * d1 + d2 * d2;
    for (int o = 16; o > 0; o >>= 1) sq += __shfl_xor_sync(0xffffffffu, sq, o);
    if ((tid & 31) == 0) red[tid >> 5] = sq;
    __syncthreads();
    float var = (red[0] + red[1] + red[2] + red[3]) * (1.f / Cn);
    float inv = rsqrtf(var + EPSn);

    out[base + tid]       = g[tid]       * d0 * inv + bb[tid];
    out[base + tid + 128] = g[tid + 128] * d1 * inv + bb[tid + 128];
    out[base + tid + 256] = g[tid + 256] * d2 * inv + bb[tid + 256];
}

// ---------------- host orchestration ----------------
extern "C" void kernel_launch(void* const* d_in, const int* in_sizes, int n_in,
                              void* d_out, int out_size)
{
    (void)in_sizes; (void)n_in; (void)out_size;
    const float* x    = (const float*)d_in[0];
    const float* q1w  = (const float*)d_in[1];
    const float* q1b  = (const float*)d_in[2];
    const float* k1w  = (const float*)d_in[3];
    const float* k1b  = (const float*)d_in[4];
    const float* v1w  = (const float*)d_in[5];
    const float* v1b  = (const float*)d_in[6];
    const float* p1w  = (const float*)d_in[7];
    const float* p1b  = (const float*)d_in[8];
    const float* ln1g = (const float*)d_in[9];
    const float* ln1b = (const float*)d_in[10];
    const float* q2w  = (const float*)d_in[11];
    const float* q2b  = (const float*)d_in[12];
    const float* k2w  = (const float*)d_in[13];
    const float* k2b  = (const float*)d_in[14];
    const float* v2w  = (const float*)d_in[15];
    const float* v2b  = (const float*)d_in[16];
    const float* p2w  = (const float*)d_in[17];
    const float* p2b  = (const float*)d_in[18];
    const float* ln2g = (const float*)d_in[19];
    const float* ln2b = (const float*)d_in[20];
    const float* f1w  = (const float*)d_in[21];
    const float* f1b  = (const float*)d_in[22];
    const float* f2w  = (const float*)d_in[23];
    const float* f2b  = (const float*)d_in[24];
    const float* ln3g = (const float*)d_in[25];
    const float* ln3b = (const float*)d_in[26];
    float* out = (float*)d_out;

    float *pwqkv, *pbqkv, *pq, *pk, *pv, *po, *pp, *pr1, *pr2, *ph;
    cudaGetSymbolAddress((void**)&pwqkv, g_wqkv);
    cudaGetSymbolAddress((void**)&pbqkv, g_bqkv);
    cudaGetSymbolAddress((void**)&pq,  g_q);
    cudaGetSymbolAddress((void**)&pk,  g_k);
    cudaGetSymbolAddress((void**)&pv,  g_v);
    cudaGetSymbolAddress((void**)&po,  g_o);
    cudaGetSymbolAddress((void**)&pp,  g_p);
    cudaGetSymbolAddress((void**)&pr1, g_r1);
    cudaGetSymbolAddress((void**)&pr2, g_r2);
    cudaGetSymbolAddress((void**)&ph,  g_h);

    const int nPack = Cn * 3 * Cn;

    auto run_layer = [&](const float* xin,
                         const float* qw, const float* qb,
                         const float* kw, const float* kb,
                         const float* vw, const float* vb,
                         const float* pw, const float* pb,
                         const float* lng, const float* lnb,
                         float* rout) {
        qkv_pack_w<<<(nPack + 255) / 256, 256>>>(qw, kw, vw, pwqkv);
        qkv_pack_b<<<(3 * Cn + 255) / 256, 256>>>(qb, kb, vb, pbqkv);
        gemm_tf32<<<dim3(3 * Cn / 128, BTn / 128), 256>>>(
            xin, pwqkv, pbqkv, nullptr, BTn, 3 * Cn, Cn, 2, pq, pk, pv);
        attn_mma<<<dim3(Tn / 64, Bn * Hn), 128>>>(pq, pk, pv, po);
        gemm_tf32<<<dim3(Cn / 128, BTn / 128), 256>>>(
            po, pw, pb, pp, BTn, Cn, Cn, 0, nullptr, nullptr, nullptr);
        ln_res_k<<<BTn, 128>>>(xin, pp, lng, lnb, rout);
    };

    run_layer(x,   q1w, q1b, k1w, k1b, v1w, v1b, p1w, p1b, ln1g, ln1b, pr1);
    run_layer(pr1, q2w, q2b, k2w, k2b, v2w, v2b, p2w, p2b, ln2g, ln2b, pr2);

    gemm_tf32<<<dim3(FFn / 128, BTn / 128), 256>>>(
        pr2, f1w, f1b, ph, BTn, FFn, Cn, 1, nullptr, nullptr, nullptr);
    gemm_tf32<<<dim3(Cn / 128, BTn / 128), 256>>>(
        ph, f2w, f2b, pp, BTn, Cn, FFn, 0, nullptr, nullptr, nullptr);
    ln_res_k<<<BTn, 128>>>(pr2, pp, ln3g, ln3b, out);
}

// round 6
// speedup vs baseline: 1.2659x; 1.0663x over previous
#include <cuda_runtime.h>
#include <math.h>

#define Bn 64
#define Tn 512
#define Cn 384
#define Hn 6
#define HDn 64
#define FFn 1536
#define BTn (Bn*Tn)
#define EPSn 1e-5f

// gemm smem strides (u32)
#define SAS 20    // A [m][k] stride: 20*gg+qq mod 32 all-distinct -> conflict-free
#define SBS 136   // B [k][n] stride: 8*qq+gg -> conflict-free

// attention smem strides (u32)
#define STQ 68
#define STK 68
#define STV 72
#define STP 36
#define AKS0 0
#define AVS0 (32*STK)
#define AKS1 (AVS0 + 32*STV)
#define AVS1 (AKS1 + 32*STK)
#define APS  (AVS1 + 32*STV)
#define ASMT (APS + 64*STP)

// ---------------- scratch ----------------
__device__ float g_wqkv[Cn*3*Cn];
__device__ float g_bqkv[3*Cn];
__device__ float g_q[(size_t)Bn*Hn*Tn*HDn];
__device__ float g_k[(size_t)Bn*Hn*Tn*HDn];
__device__ float g_v[(size_t)Bn*Hn*Tn*HDn];
__device__ float g_o[(size_t)BTn*Cn];
__device__ float g_p[(size_t)BTn*Cn];
__device__ float g_r1[(size_t)BTn*Cn];
__device__ float g_r2[(size_t)BTn*Cn];
__device__ float g_h[(size_t)BTn*FFn];

// ---------------- packs ----------------
__global__ void qkv_pack_w(const float* __restrict__ qw, const float* __restrict__ kw,
                           const float* __restrict__ vw, float* __restrict__ o) {
    int idx = blockIdx.x * blockDim.x + threadIdx.x;
    if (idx >= Cn * 3 * Cn) return;
    int c = idx / (3 * Cn);
    int col = idx % (3 * Cn);
    int mat = col / Cn;
    int local = col % Cn;
    int h = local >> 6, d = local & 63;
    const float* w = (mat == 0) ? qw : (mat == 1) ? kw : vw;
    o[idx] = w[((size_t)h * Cn + c) * HDn + d];
}
__global__ void qkv_pack_b(const float* __restrict__ qb, const float* __restrict__ kb,
                           const float* __restrict__ vb, float* __restrict__ o) {
    int i = threadIdx.x + blockIdx.x * blockDim.x;
    if (i >= 3 * Cn) return;
    const float* b = (i < Cn) ? qb : (i < 2 * Cn) ? kb : vb;
    o[i] = b[i % Cn];
}

// ---------------- tf32 / async helpers ----------------
__device__ __forceinline__ unsigned f2tf(float x) {
    unsigned r; asm("cvt.rna.tf32.f32 %0, %1;" : "=r"(r) : "f"(x)); return r;
}
__device__ __forceinline__ void mma8(float* d, const unsigned* a, const unsigned* b) {
    asm("mma.sync.aligned.m16n8k8.row.col.f32.tf32.tf32.f32 "
        "{%0,%1,%2,%3},{%4,%5,%6,%7},{%8,%9},{%0,%1,%2,%3};"
        : "+f"(d[0]), "+f"(d[1]), "+f"(d[2]), "+f"(d[3])
        : "r"(a[0]), "r"(a[1]), "r"(a[2]), "r"(a[3]), "r"(b[0]), "r"(b[1]));
}
__device__ __forceinline__ void cp_async16(void* smem_dst, const void* gsrc) {
    unsigned saddr = (unsigned)__cvta_generic_to_shared(smem_dst);
    asm volatile("cp.async.ca.shared.global [%0], [%1], 16;\n" :: "r"(saddr), "l"(gsrc));
}
#define CP_COMMIT() asm volatile("cp.async.commit_group;\n" ::: "memory")
#define CP_WAIT1()  asm volatile("cp.async.wait_group 1;\n" ::: "memory")
#define CP_WAIT0()  asm volatile("cp.async.wait_group 0;\n" ::: "memory")

// ---------------- tf32 GEMM: cp.async 3-stage pipeline -------------------------
// 256 thr, warps 2x4, warp tile 64x32, block 128x128, K-step 16.
// smem holds raw fp32 bits; mma.tf32 truncates. Inner loop pure LDS+MMA.
// flags: bit0 relu; bit1 qkv-scatter (+rope on q/k)
__global__ __launch_bounds__(256) void gemm_tf32(
    const float* __restrict__ A, const float* __restrict__ Bm,
    const float* __restrict__ bias, float* __restrict__ Cout,
    int M, int N, int K, int flags,
    float* __restrict__ oq, float* __restrict__ ok, float* __restrict__ ov)
{
    __shared__ unsigned As[3][128 * SAS];
    __shared__ unsigned Bs[3][16 * SBS];

    const int tid = threadIdx.x;
    const int lane = tid & 31, warp = tid >> 5;
    const int warpM = warp >> 2, warpN = warp & 3;   // 2 x 4
    const int bm = blockIdx.y * 128, bn = blockIdx.x * 128;
    const int qq = lane & 3, gg = lane >> 2;

    // cp.async mappings: A 128 rows x 16k (2 thr/row, 8 floats each);
    //                    B 16 rows x 128n (16 thr/row, 8 floats each)
    const int aRow = tid >> 1, aCol = (tid & 1) * 8;
    const int bK = tid >> 4, bCol = (tid & 15) * 8;
    const float* Ap = A + (size_t)(bm + aRow) * K + aCol;
    const float* Bp = Bm + (size_t)bK * N + bn + bCol;

    float acc[4][4][4];
#pragma unroll
    for (int i = 0; i < 4; i++)
#pragma unroll
        for (int j = 0; j < 4; j++)
#pragma unroll
            for (int r = 0; r < 4; r++) acc[i][j][r] = 0.f;

    const int KT = K >> 4;

    // prologue: stages 0, 1
    {
        unsigned* as = As[0]; unsigned* bs = Bs[0];
        cp_async16(as + aRow * SAS + aCol,     Ap);
        cp_async16(as + aRow * SAS + aCol + 4, Ap + 4);
        cp_async16(bs + bK * SBS + bCol,       Bp);
        cp_async16(bs + bK * SBS + bCol + 4,   Bp + 4);
    }
    CP_COMMIT();
    if (KT > 1) {
        unsigned* as = As[1]; unsigned* bs = Bs[1];
        cp_async16(as + aRow * SAS + aCol,     Ap + 16);
        cp_async16(as + aRow * SAS + aCol + 4, Ap + 20);
        cp_async16(bs + bK * SBS + bCol,       Bp + (size_t)16 * N);
        cp_async16(bs + bK * SBS + bCol + 4,   Bp + (size_t)16 * N + 4);
    }
    CP_COMMIT();

    for (int kt = 0; kt < KT; kt++) {
        CP_WAIT1();
        __syncthreads();

        if (kt + 2 < KT) {
            int st = (kt + 2) % 3;
            unsigned* as = As[st]; unsigned* bs = Bs[st];
            const float* ap = Ap + (size_t)(kt + 2) * 16;
            const float* bp = Bp + (size_t)(kt + 2) * 16 * N;
            cp_async16(as + aRow * SAS + aCol,     ap);
            cp_async16(as + aRow * SAS + aCol + 4, ap + 4);
            cp_async16(bs + bK * SBS + bCol,       bp);
            cp_async16(bs + bK * SBS + bCol + 4,   bp + 4);
        }
        CP_COMMIT();

        const unsigned* as = As[kt % 3];
        const unsigned* bs = Bs[kt % 3];
#pragma unroll
        for (int kk = 0; kk < 16; kk += 8) {
            unsigned af[4][4], bf[4][2];
#pragma unroll
            for (int mi = 0; mi < 4; mi++) {
                int m0 = warpM * 64 + mi * 16 + gg;
                af[mi][0] = as[(m0)     * SAS + kk + qq];
                af[mi][1] = as[(m0 + 8) * SAS + kk + qq];
                af[mi][2] = as[(m0)     * SAS + kk + qq + 4];
                af[mi][3] = as[(m0 + 8) * SAS + kk + qq + 4];
            }
#pragma unroll
            for (int ni = 0; ni < 4; ni++) {
                int n0 = warpN * 32 + ni * 8 + gg;
                bf[ni][0] = bs[(kk + qq) * SBS + n0];
                bf[ni][1] = bs[(kk + qq + 4) * SBS + n0];
            }
#pragma unroll
            for (int mi = 0; mi < 4; mi++)
#pragma unroll
                for (int ni = 0; ni < 4; ni++)
                    mma8(acc[mi][ni], af[mi], bf[ni]);
        }
    }

    // -------- epilogue --------
    const bool relu = (flags & 1) != 0;
    const bool qkv = (flags & 2) != 0;

#pragma unroll
    for (int mi = 0; mi < 4; mi++) {
        int row0 = bm + warpM * 64 + mi * 16 + gg;
        float sn[2], cs[2];
        if (qkv) {
            sincosf((float)(row0 & 511), &sn[0], &cs[0]);
            sincosf((float)((row0 + 8) & 511), &sn[1], &cs[1]);
        }
#pragma unroll
        for (int ni = 0; ni < 4; ni++) {
            int col = bn + warpN * 32 + ni * 8 + qq * 2;
            float b0 = bias[col], b1 = bias[col + 1];
#pragma unroll
            for (int half = 0; half < 2; half++) {
                int row = row0 + half * 8;
                float xr = acc[mi][ni][half * 2 + 0] + b0;
                float xi = acc[mi][ni][half * 2 + 1] + b1;
                if (qkv) {
                    int mat = col / Cn;
                    if (mat < 2) {
                        float nr = cs[half] * xr - sn[half] * xi;
                        float ni2 = sn[half] * xr + cs[half] * xi;
                        xr = nr; xi = ni2;
                    }
                    int local = col - mat * Cn;
                    int h = local >> 6, d = local & 63;
                    int bb = row >> 9, t = row & 511;
                    float* dst = (mat == 0) ? oq : (mat == 1) ? ok : ov;
                    float2* p = (float2*)(dst + (((size_t)(bb * Hn + h) * Tn + t) * HDn + d));
                    *p = make_float2(xr, xi);
                } else {
                    if (relu) { xr = fmaxf(xr, 0.f); xi = fmaxf(xi, 0.f); }
                    float2* p = (float2*)(Cout + (size_t)row * N + col);
                    *p = make_float2(xr, xi);
                }
            }
        }
    }
}

// ---------------- tensor-core causal flash attention (unchanged from R5) ----------
__global__ __launch_bounds__(128) void attn_mma(
    const float* __restrict__ q, const float* __restrict__ k,
    const float* __restrict__ v, float* __restrict__ o)
{
    __shared__ unsigned sm[ASMT];
    unsigned* Ps = sm + APS;

    const int bh = blockIdx.y;
    const int qt = gridDim.x - 1 - blockIdx.x;
    const int tid = threadIdx.x;
    const int warp = tid >> 5, lane = tid & 31;
    const int gg = lane >> 2, qq = lane & 3;
    const size_t base = (size_t)bh * Tn * HDn;
    const int q0 = qt * 64;
    const float scale = 0.051031036307982884f;
    const int ktiles = 2 * qt + 2;

    {
        unsigned* kd = sm + AKS0;
        unsigned* vd = sm + AVS0;
#pragma unroll
        for (int i = 0; i < 4; i++) {
            int idx = i * 128 + tid;
            int r = idx >> 4, c4 = (idx & 15) * 4;
            cp_async16(kd + r * STK + c4, k + base + (size_t)r * 64 + c4);
            cp_async16(vd + r * STV + c4, v + base + (size_t)r * 64 + c4);
        }
        CP_COMMIT();
    }

    unsigned* qstage = sm + AKS1;
    for (int i = tid; i < 64 * 16; i += 128) {
        int r = i >> 4, d4 = (i & 15) * 4;
        float4 t4 = *(const float4*)(q + base + (size_t)(q0 + r) * 64 + d4);
        uint4 u4 = make_uint4(f2tf(t4.x * scale), f2tf(t4.y * scale),
                              f2tf(t4.z * scale), f2tf(t4.w * scale));
        *(uint4*)(qstage + r * STQ + d4) = u4;
    }
    __syncthreads();

    unsigned qf[8][4];
    {
        const unsigned* qr = qstage + (warp * 16 + gg) * STQ;
#pragma unroll
        for (int ks = 0; ks < 8; ks++) {
            qf[ks][0] = qr[ks * 8 + qq];
            qf[ks][1] = qr[8 * STQ + ks * 8 + qq];
            qf[ks][2] = qr[ks * 8 + qq + 4];
            qf[ks][3] = qr[8 * STQ + ks * 8 + qq + 4];
        }
    }
    __syncthreads();
    CP_WAIT0();
    __syncthreads();

    float oacc[8][4];
#pragma unroll
    for (int i = 0; i < 8; i++)
#pragma unroll
        for (int r = 0; r < 4; r++) oacc[i][r] = 0.f;
    float m0 = -INFINITY, m1 = -INFINITY, l0 = 0.f, l1 = 0.f;

    const int row0g = q0 + warp * 16 + gg;
    const int row1g = row0g + 8;

    for (int kt = 0; kt < ktiles; kt++) {
        const int kbase = kt * 32;
        const unsigned* Ks = sm + ((kt & 1) ? AKS1 : AKS0);
        const unsigned* Vs = sm + ((kt & 1) ? AVS1 : AVS0);

        if (kt + 1 < ktiles) {
            unsigned* kd = sm + (((kt + 1) & 1) ? AKS1 : AKS0);
            unsigned* vd = sm + (((kt + 1) & 1) ? AVS1 : AVS0);
            const size_t nb = base + (size_t)(kbase + 32) * 64;
#pragma unroll
            for (int i = 0; i < 4; i++) {
                int idx = i * 128 + tid;
                int r = idx >> 4, c4 = (idx & 15) * 4;
                cp_async16(kd + r * STK + c4, k + nb + (size_t)r * 64 + c4);
                cp_async16(vd + r * STV + c4, v + nb + (size_t)r * 64 + c4);
            }
            CP_COMMIT();
        }

        float s[4][4];
#pragma unroll
        for (int nt = 0; nt < 4; nt++)
#pragma unroll
            for (int r = 0; r < 4; r++) s[nt][r] = 0.f;
#pragma unroll
        for (int ks = 0; ks < 8; ks++) {
            unsigned bf[4][2];
#pragma unroll
            for (int nt = 0; nt < 4; nt++) {
                bf[nt][0] = Ks[(nt * 8 + gg) * STK + ks * 8 + qq];
                bf[nt][1] = Ks[(nt * 8 + gg) * STK + ks * 8 + qq + 4];
            }
#pragma unroll
            for (int nt = 0; nt < 4; nt++) mma8(s[nt], qf[ks], bf[nt]);
        }

        if (kt >= 2 * qt) {
#pragma unroll
            for (int nt = 0; nt < 4; nt++) {
                int c0 = kbase + nt * 8 + 2 * qq;
                if (c0 > row0g)     s[nt][0] = -1e30f;
                if (c0 + 1 > row0g) s[nt][1] = -1e30f;
                if (c0 > row1g)     s[nt][2] = -1e30f;
                if (c0 + 1 > row1g) s[nt][3] = -1e30f;
            }
        }

        float rm0 = -1e30f, rm1 = -1e30f;
#pragma unroll
        for (int nt = 0; nt < 4; nt++) {
            rm0 = fmaxf(rm0, fmaxf(s[nt][0], s[nt][1]));
            rm1 = fmaxf(rm1, fmaxf(s[nt][2], s[nt][3]));
        }
        rm0 = fmaxf(rm0, __shfl_xor_sync(0xffffffffu, rm0, 1));
        rm0 = fmaxf(rm0, __shfl_xor_sync(0xffffffffu, rm0, 2));
        rm1 = fmaxf(rm1, __shfl_xor_sync(0xffffffffu, rm1, 1));
        rm1 = fmaxf(rm1, __shfl_xor_sync(0xffffffffu, rm1, 2));
        float nm0 = fmaxf(m0, rm0), nm1 = fmaxf(m1, rm1);
        float corr0 = __expf(m0 - nm0), corr1 = __expf(m1 - nm1);
        float rs0 = 0.f, rs1 = 0.f;
#pragma unroll
        for (int nt = 0; nt < 4; nt++) {
            s[nt][0] = __expf(s[nt][0] - nm0);
            s[nt][1] = __expf(s[nt][1] - nm0);
            s[nt][2] = __expf(s[nt][2] - nm1);
            s[nt][3] = __expf(s[nt][3] - nm1);
            rs0 += s[nt][0] + s[nt][1];
            rs1 += s[nt][2] + s[nt][3];
        }
        rs0 += __shfl_xor_sync(0xffffffffu, rs0, 1);
        rs0 += __shfl_xor_sync(0xffffffffu, rs0, 2);
        rs1 += __shfl_xor_sync(0xffffffffu, rs1, 1);
        rs1 += __shfl_xor_sync(0xffffffffu, rs1, 2);
        l0 = l0 * corr0 + rs0;
        l1 = l1 * corr1 + rs1;
        m0 = nm0; m1 = nm1;
#pragma unroll
        for (int nt = 0; nt < 8; nt++) {
            oacc[nt][0] *= corr0; oacc[nt][1] *= corr0;
            oacc[nt][2] *= corr1; oacc[nt][3] *= corr1;
        }

        {
            unsigned* pr = Ps + (warp * 16 + gg) * STP;
#pragma unroll
            for (int nt = 0; nt < 4; nt++) {
                *(uint2*)(pr + nt * 8 + 2 * qq) = make_uint2(f2tf(s[nt][0]), f2tf(s[nt][1]));
                *(uint2*)(pr + 8 * STP + nt * 8 + 2 * qq) = make_uint2(f2tf(s[nt][2]), f2tf(s[nt][3]));
            }
        }
        __syncwarp();

#pragma unroll
        for (int ks = 0; ks < 4; ks++) {
            unsigned af[4];
            const unsigned* pr = Ps + (warp * 16 + gg) * STP + ks * 8;
            af[0] = pr[qq];
            af[1] = pr[8 * STP + qq];
            af[2] = pr[qq + 4];
            af[3] = pr[8 * STP + qq + 4];
#pragma unroll
            for (int nt = 0; nt < 8; nt++) {
                unsigned bf2[2];
                bf2[0] = Vs[(ks * 8 + qq) * STV + nt * 8 + gg];
                bf2[1] = Vs[(ks * 8 + qq + 4) * STV + nt * 8 + gg];
                mma8(oacc[nt], af, bf2);
            }
        }

        if (kt + 1 < ktiles) {
            CP_WAIT0();
            __syncthreads();
        }
    }

    const float inv0 = 1.f / l0, inv1 = 1.f / l1;
    const int b = bh / Hn, h = bh % Hn;
    float* p0 = o + ((size_t)(b * Tn + row0g)) * Cn + h * 64;
    float* p1 = o + ((size_t)(b * Tn + row1g)) * Cn + h * 64;
#pragma unroll
    for (int nt = 0; nt < 8; nt++) {
        *(float2*)(p0 + nt * 8 + 2 * qq) = make_float2(oacc[nt][0] * inv0, oacc[nt][1] * inv0);
        *(float2*)(p1 + nt * 8 + 2 * qq) = make_float2(oacc[nt][2] * inv1, oacc[nt][3] * inv1);
    }
}

// ---------------- fused residual + LayerNorm ----------------
__global__ __launch_bounds__(128) void ln_res_k(
    const float* __restrict__ x, const float* __restrict__ y,
    const float* __restrict__ g, const float* __restrict__ bb,
    float* __restrict__ out)
{
    __shared__ float red[4];
    const int row = blockIdx.x;
    const int tid = threadIdx.x;
    const size_t base = (size_t)row * Cn;
    float v0 = x[base + tid]       + y[base + tid];
    float v1 = x[base + tid + 128] + y[base + tid + 128];
    float v2 = x[base + tid + 256] + y[base + tid + 256];

    float s = v0 + v1 + v2;
    for (int o = 16; o > 0; o >>= 1) s += __shfl_xor_sync(0xffffffffu, s, o);
    if ((tid & 31) == 0) red[tid >> 5] = s;
    __syncthreads();
    float mean = (red[0] + red[1] + red[2] + red[3]) * (1.f / Cn);
    __syncthreads();

    float d0 = v0 - mean, d1 = v1 - mean, d2 = v2 - mean;
    float sq = d0 * d0 + d1 * d1 + d2 * d2;
    for (int o = 16; o > 0; o >>= 1) sq += __shfl_xor_sync(0xffffffffu, sq, o);
    if ((tid & 31) == 0) red[tid >> 5] = sq;
    __syncthreads();
    float var = (red[0] + red[1] + red[2] + red[3]) * (1.f / Cn);
    float inv = rsqrtf(var + EPSn);

    out[base + tid]       = g[tid]       * d0 * inv + bb[tid];
    out[base + tid + 128] = g[tid + 128] * d1 * inv + bb[tid + 128];
    out[base + tid + 256] = g[tid + 256] * d2 * inv + bb[tid + 256];
}

// ---------------- host orchestration ----------------
extern "C" void kernel_launch(void* const* d_in, const int* in_sizes, int n_in,
                              void* d_out, int out_size)
{
    (void)in_sizes; (void)n_in; (void)out_size;
    const float* x    = (const float*)d_in[0];
    const float* q1w  = (const float*)d_in[1];
    const float* q1b  = (const float*)d_in[2];
    const float* k1w  = (const float*)d_in[3];
    const float* k1b  = (const float*)d_in[4];
    const float* v1w  = (const float*)d_in[5];
    const float* v1b  = (const float*)d_in[6];
    const float* p1w  = (const float*)d_in[7];
    const float* p1b  = (const float*)d_in[8];
    const float* ln1g = (const float*)d_in[9];
    const float* ln1b = (const float*)d_in[10];
    const float* q2w  = (const float*)d_in[11];
    const float* q2b  = (const float*)d_in[12];
    const float* k2w  = (const float*)d_in[13];
    const float* k2b  = (const float*)d_in[14];
    const float* v2w  = (const float*)d_in[15];
    const float* v2b  = (const float*)d_in[16];
    const float* p2w  = (const float*)d_in[17];
    const float* p2b  = (const float*)d_in[18];
    const float* ln2g = (const float*)d_in[19];
    const float* ln2b = (const float*)d_in[20];
    const float* f1w  = (const float*)d_in[21];
    const float* f1b  = (const float*)d_in[22];
    const float* f2w  = (const float*)d_in[23];
    const float* f2b  = (const float*)d_in[24];
    const float* ln3g = (const float*)d_in[25];
    const float* ln3b = (const float*)d_in[26];
    float* out = (float*)d_out;

    float *pwqkv, *pbqkv, *pq, *pk, *pv, *po, *pp, *pr1, *pr2, *ph;
    cudaGetSymbolAddress((void**)&pwqkv, g_wqkv);
    cudaGetSymbolAddress((void**)&pbqkv, g_bqkv);
    cudaGetSymbolAddress((void**)&pq,  g_q);
    cudaGetSymbolAddress((void**)&pk,  g_k);
    cudaGetSymbolAddress((void**)&pv,  g_v);
    cudaGetSymbolAddress((void**)&po,  g_o);
    cudaGetSymbolAddress((void**)&pp,  g_p);
    cudaGetSymbolAddress((void**)&pr1, g_r1);
    cudaGetSymbolAddress((void**)&pr2, g_r2);
    cudaGetSymbolAddress((void**)&ph,  g_h);

    const int nPack = Cn * 3 * Cn;

    auto run_layer = [&](const float* xin,
                         const float* qw, const float* qb,
                         const float* kw, const float* kb,
                         const float* vw, const float* vb,
                         const float* pw, const float* pb,
                         const float* lng, const float* lnb,
                         float* rout) {
        qkv_pack_w<<<(nPack + 255) / 256, 256>>>(qw, kw, vw, pwqkv);
        qkv_pack_b<<<(3 * Cn + 255) / 256, 256>>>(qb, kb, vb, pbqkv);
        gemm_tf32<<<dim3(3 * Cn / 128, BTn / 128), 256>>>(
            xin, pwqkv, pbqkv, nullptr, BTn, 3 * Cn, Cn, 2, pq, pk, pv);
        attn_mma<<<dim3(Tn / 64, Bn * Hn), 128>>>(pq, pk, pv, po);
        gemm_tf32<<<dim3(Cn / 128, BTn / 128), 256>>>(
            po, pw, pb, pp, BTn, Cn, Cn, 0, nullptr, nullptr, nullptr);
        ln_res_k<<<BTn, 128>>>(xin, pp, lng, lnb, rout);
    };

    run_layer(x,   q1w, q1b, k1w, k1b, v1w, v1b, p1w, p1b, ln1g, ln1b, pr1);
    run_layer(pr1, q2w, q2b, k2w, k2b, v2w, v2b, p2w, p2b, ln2g, ln2b, pr2);

    gemm_tf32<<<dim3(FFn / 128, BTn / 128), 256>>>(
        pr2, f1w, f1b, ph, BTn, FFn, Cn, 1, nullptr, nullptr, nullptr);
    gemm_tf32<<<dim3(Cn / 128, BTn / 128), 256>>>(
        ph, f2w, f2b, pp, BTn, Cn, FFn, 0, nullptr, nullptr, nullptr);
    ln_res_k<<<BTn, 128>>>(pr2, pp, ln3g, ln3b, out);
}

// round 7
// speedup vs baseline: 1.7185x; 1.3576x over previous
#include <cuda_runtime.h>
#include <cuda_fp16.h>
#include <math.h>

#define Bn 64
#define Tn 512
#define Cn 384
#define Hn 6
#define HDn 64
#define FFn 1536
#define BTn (Bn*Tn)
#define EPSn 1e-5f

// fp16 gemm smem stride (u32 words per row of 32 halves + pad)
#define SWS 20    // (20*gg + qq) mod 32 all-distinct -> conflict-free

// attention smem strides (u32)
#define STQ 68
#define STK 68
#define STV 72
#define STP 36
#define AKS0 0
#define AVS0 (32*STK)
#define AKS1 (AVS0 + 32*STV)
#define AVS1 (AKS1 + 32*STK)
#define APS  (AVS1 + 32*STV)
#define ASMT (APS + 64*STP)

// ---------------- scratch ----------------
__device__ __half g_wqkv16[3*Cn*Cn];     // [n=3C][k=C]
__device__ __half g_wp16[Cn*Cn];         // [n][k]
__device__ __half g_wf1t[FFn*Cn];        // [n=FF][k=C]
__device__ __half g_wf2t[Cn*FFn];        // [n=C][k=FF]
__device__ float  g_bqkv[3*Cn];
__device__ __half g_x16[(size_t)BTn*Cn];
__device__ __half g_o16[(size_t)BTn*Cn];
__device__ __half g_r16[(size_t)BTn*Cn];
__device__ __half g_h16[(size_t)BTn*FFn];
__device__ float g_q[(size_t)Bn*Hn*Tn*HDn];
__device__ float g_k[(size_t)Bn*Hn*Tn*HDn];
__device__ float g_v[(size_t)Bn*Hn*Tn*HDn];
__device__ float g_p[(size_t)BTn*Cn];
__device__ float g_r1[(size_t)BTn*Cn];
__device__ float g_r2[(size_t)BTn*Cn];

// ---------------- packs ----------------
// qkv weights [H,C,HD]x3 -> fp16 [n=3C][k=C]
__global__ void qkv_pack_w16(const float* __restrict__ qw, const float* __restrict__ kw,
                             const float* __restrict__ vw, __half* __restrict__ o) {
    int idx = blockIdx.x * blockDim.x + threadIdx.x;
    if (idx >= 3 * Cn * Cn) return;
    int n = idx / Cn;           // output col 0..1151
    int k = idx % Cn;           // input channel
    int mat = n / Cn;
    int local = n % Cn;
    int h = local >> 6, d = local & 63;
    const float* w = (mat == 0) ? qw : (mat == 1) ? kw : vw;
    o[idx] = __float2half(w[((size_t)h * Cn + k) * HDn + d]);
}
__global__ void qkv_pack_b(const float* __restrict__ qb, const float* __restrict__ kb,
                           const float* __restrict__ vb, float* __restrict__ o) {
    int i = threadIdx.x + blockIdx.x * blockDim.x;
    if (i >= 3 * Cn) return;
    const float* b = (i < Cn) ? qb : (i < 2 * Cn) ? kb : vb;
    o[i] = b[i % Cn];
}
// weight [K][N] fp32 -> [N][K] fp16
__global__ void wt_pack16(const float* __restrict__ w, __half* __restrict__ o, int N, int K) {
    int idx = blockIdx.x * blockDim.x + threadIdx.x;
    if (idx >= N * K) return;
    int n = idx / K, k = idx % K;
    o[idx] = __float2half(w[(size_t)k * N + n]);
}
// fp32 -> fp16 copy
__global__ void f2h_k(const float* __restrict__ a, __half* __restrict__ o, int n) {
    int i = blockIdx.x * blockDim.x + threadIdx.x;
    if (i < n) o[i] = __float2half(a[i]);
}

// ---------------- mma / async helpers ----------------
__device__ __forceinline__ unsigned f2tf(float x) {
    unsigned r; asm("cvt.rna.tf32.f32 %0, %1;" : "=r"(r) : "f"(x)); return r;
}
__device__ __forceinline__ void mma8(float* d, const unsigned* a, const unsigned* b) {
    asm("mma.sync.aligned.m16n8k8.row.col.f32.tf32.tf32.f32 "
        "{%0,%1,%2,%3},{%4,%5,%6,%7},{%8,%9},{%0,%1,%2,%3};"
        : "+f"(d[0]), "+f"(d[1]), "+f"(d[2]), "+f"(d[3])
        : "r"(a[0]), "r"(a[1]), "r"(a[2]), "r"(a[3]), "r"(b[0]), "r"(b[1]));
}
__device__ __forceinline__ void mma16(float* d, const unsigned* a, const unsigned* b) {
    asm("mma.sync.aligned.m16n8k16.row.col.f32.f16.f16.f32 "
        "{%0,%1,%2,%3},{%4,%5,%6,%7},{%8,%9},{%0,%1,%2,%3};"
        : "+f"(d[0]), "+f"(d[1]), "+f"(d[2]), "+f"(d[3])
        : "r"(a[0]), "r"(a[1]), "r"(a[2]), "r"(a[3]), "r"(b[0]), "r"(b[1]));
}
__device__ __forceinline__ void cp_async16(void* smem_dst, const void* gsrc) {
    unsigned saddr = (unsigned)__cvta_generic_to_shared(smem_dst);
    asm volatile("cp.async.ca.shared.global [%0], [%1], 16;\n" :: "r"(saddr), "l"(gsrc));
}
#define CP_COMMIT() asm volatile("cp.async.commit_group;\n" ::: "memory")
#define CP_WAIT1()  asm volatile("cp.async.wait_group 1;\n" ::: "memory")
#define CP_WAIT0()  asm volatile("cp.async.wait_group 0;\n" ::: "memory")

// ---------------- fp16 GEMM: C[M,N] = A[M,K] @ B'[N,K]^T + bias ------------------
// A fp16 row-major [M][K]; B fp16 [N][K]. 256 thr, warps 2x4, warp 64x32,
// block 128x128, K-step 32, cp.async 3-stage. fp32 accum.
// flags: 0 = fp32 out; 1 = relu + fp16 out (Cout16); 2 = qkv scatter fp32 + rope
__global__ __launch_bounds__(256) void gemm_f16(
    const __half* __restrict__ A, const __half* __restrict__ Bm,
    const float* __restrict__ bias, float* __restrict__ Cout,
    __half* __restrict__ Cout16,
    int M, int N, int K, int flags,
    float* __restrict__ oq, float* __restrict__ ok, float* __restrict__ ov)
{
    __shared__ __align__(16) unsigned As[3][128 * SWS];
    __shared__ __align__(16) unsigned Bs[3][128 * SWS];

    const int tid = threadIdx.x;
    const int lane = tid & 31, warp = tid >> 5;
    const int warpM = warp >> 2, warpN = warp & 3;   // 2 x 4
    const int bm = blockIdx.y * 128, bn = blockIdx.x * 128;
    const int qq = lane & 3, gg = lane >> 2;

    // staging: 2 threads per row, each 16 halves (2 x cp.async16)
    const int sRow = tid >> 1;               // 0..127
    const int sOff = (tid & 1) * 8;          // word offset 0 / 8
    const __half* Ap = A + (size_t)(bm + sRow) * K + (tid & 1) * 16;
    const __half* Bp = Bm + (size_t)(bn + sRow) * K + (tid & 1) * 16;

    float acc[4][4][4];
#pragma unroll
    for (int i = 0; i < 4; i++)
#pragma unroll
        for (int j = 0; j < 4; j++)
#pragma unroll
            for (int r = 0; r < 4; r++) acc[i][j][r] = 0.f;

    const int KT = K >> 5;

    // prologue: stages 0, 1
    {
        unsigned* as = As[0]; unsigned* bs = Bs[0];
        cp_async16(as + sRow * SWS + sOff,     Ap);
        cp_async16(as + sRow * SWS + sOff + 4, Ap + 8);
        cp_async16(bs + sRow * SWS + sOff,     Bp);
        cp_async16(bs + sRow * SWS + sOff + 4, Bp + 8);
    }
    CP_COMMIT();
    {
        unsigned* as = As[1]; unsigned* bs = Bs[1];
        cp_async16(as + sRow * SWS + sOff,     Ap + 32);
        cp_async16(as + sRow * SWS + sOff + 4, Ap + 40);
        cp_async16(bs + sRow * SWS + sOff,     Bp + 32);
        cp_async16(bs + sRow * SWS + sOff + 4, Bp + 40);
    }
    CP_COMMIT();

    for (int kt = 0; kt < KT; kt++) {
        CP_WAIT1();
        __syncthreads();

        if (kt + 2 < KT) {
            int st = (kt + 2) % 3;
            unsigned* as = As[st]; unsigned* bs = Bs[st];
            const __half* ap = Ap + (size_t)(kt + 2) * 32;
            const __half* bp = Bp + (size_t)(kt + 2) * 32;
            cp_async16(as + sRow * SWS + sOff,     ap);
            cp_async16(as + sRow * SWS + sOff + 4, ap + 8);
            cp_async16(bs + sRow * SWS + sOff,     bp);
            cp_async16(bs + sRow * SWS + sOff + 4, bp + 8);
        }
        CP_COMMIT();

        const unsigned* as = As[kt % 3];
        const unsigned* bs = Bs[kt % 3];
#pragma unroll
        for (int ko = 0; ko < 16; ko += 8) {    // two k16 steps per stage
            unsigned af[4][4], bf[4][2];
#pragma unroll
            for (int mi = 0; mi < 4; mi++) {
                int m0 = warpM * 64 + mi * 16 + gg;
                af[mi][0] = as[(m0)     * SWS + ko + qq];
                af[mi][1] = as[(m0 + 8) * SWS + ko + qq];
                af[mi][2] = as[(m0)     * SWS + ko + qq + 4];
                af[mi][3] = as[(m0 + 8) * SWS + ko + qq + 4];
            }
#pragma unroll
            for (int ni = 0; ni < 4; ni++) {
                int n0 = warpN * 32 + ni * 8 + gg;
                bf[ni][0] = bs[(n0) * SWS + ko + qq];
                bf[ni][1] = bs[(n0) * SWS + ko + qq + 4];
            }
#pragma unroll
            for (int mi = 0; mi < 4; mi++)
#pragma unroll
                for (int ni = 0; ni < 4; ni++)
                    mma16(acc[mi][ni], af[mi], bf[ni]);
        }
    }

    // -------- epilogue --------
#pragma unroll
    for (int mi = 0; mi < 4; mi++) {
        int row0 = bm + warpM * 64 + mi * 16 + gg;
        float sn[2], cs[2];
        if (flags == 2) {
            sincosf((float)(row0 & 511), &sn[0], &cs[0]);
            sincosf((float)((row0 + 8) & 511), &sn[1], &cs[1]);
        }
#pragma unroll
        for (int ni = 0; ni < 4; ni++) {
            int col = bn + warpN * 32 + ni * 8 + qq * 2;
            float b0 = bias[col], b1 = bias[col + 1];
#pragma unroll
            for (int half = 0; half < 2; half++) {
                int row = row0 + half * 8;
                float xr = acc[mi][ni][half * 2 + 0] + b0;
                float xi = acc[mi][ni][half * 2 + 1] + b1;
                if (flags == 2) {
                    int mat = col / Cn;
                    if (mat < 2) {
                        float nr = cs[half] * xr - sn[half] * xi;
                        float ni2 = sn[half] * xr + cs[half] * xi;
                        xr = nr; xi = ni2;
                    }
                    int local = col - mat * Cn;
                    int h = local >> 6, d = local & 63;
                    int bb = row >> 9, t = row & 511;
                    float* dst = (mat == 0) ? oq : (mat == 1) ? ok : ov;
                    float2* p = (float2*)(dst + (((size_t)(bb * Hn + h) * Tn + t) * HDn + d));
                    *p = make_float2(xr, xi);
                } else if (flags == 1) {
                    xr = fmaxf(xr, 0.f); xi = fmaxf(xi, 0.f);
                    __half2* p = (__half2*)(Cout16 + (size_t)row * N + col);
                    *p = __floats2half2_rn(xr, xi);
                } else {
                    float2* p = (float2*)(Cout + (size_t)row * N + col);
                    *p = make_float2(xr, xi);
                }
            }
        }
    }
}

// ---------------- tensor-core causal flash attention (fp32 in, fp16 out) ----------
__global__ __launch_bounds__(128) void attn_mma(
    const float* __restrict__ q, const float* __restrict__ k,
    const float* __restrict__ v, __half* __restrict__ o)
{
    __shared__ unsigned sm[ASMT];
    unsigned* Ps = sm + APS;

    const int bh = blockIdx.y;
    const int qt = gridDim.x - 1 - blockIdx.x;
    const int tid = threadIdx.x;
    const int warp = tid >> 5, lane = tid & 31;
    const int gg = lane >> 2, qq = lane & 3;
    const size_t base = (size_t)bh * Tn * HDn;
    const int q0 = qt * 64;
    const float scale = 0.051031036307982884f;
    const int ktiles = 2 * qt + 2;

    {
        unsigned* kd = sm + AKS0;
        unsigned* vd = sm + AVS0;
#pragma unroll
        for (int i = 0; i < 4; i++) {
            int idx = i * 128 + tid;
            int r = idx >> 4, c4 = (idx & 15) * 4;
            cp_async16(kd + r * STK + c4, k + base + (size_t)r * 64 + c4);
            cp_async16(vd + r * STV + c4, v + base + (size_t)r * 64 + c4);
        }
        CP_COMMIT();
    }

    unsigned* qstage = sm + AKS1;
    for (int i = tid; i < 64 * 16; i += 128) {
        int r = i >> 4, d4 = (i & 15) * 4;
        float4 t4 = *(const float4*)(q + base + (size_t)(q0 + r) * 64 + d4);
        uint4 u4 = make_uint4(f2tf(t4.x * scale), f2tf(t4.y * scale),
                              f2tf(t4.z * scale), f2tf(t4.w * scale));
        *(uint4*)(qstage + r * STQ + d4) = u4;
    }
    __syncthreads();

    unsigned qf[8][4];
    {
        const unsigned* qr = qstage + (warp * 16 + gg) * STQ;
#pragma unroll
        for (int ks = 0; ks < 8; ks++) {
            qf[ks][0] = qr[ks * 8 + qq];
            qf[ks][1] = qr[8 * STQ + ks * 8 + qq];
            qf[ks][2] = qr[ks * 8 + qq + 4];
            qf[ks][3] = qr[8 * STQ + ks * 8 + qq + 4];
        }
    }
    __syncthreads();
    CP_WAIT0();
    __syncthreads();

    float oacc[8][4];
#pragma unroll
    for (int i = 0; i < 8; i++)
#pragma unroll
        for (int r = 0; r < 4; r++) oacc[i][r] = 0.f;
    float m0 = -INFINITY, m1 = -INFINITY, l0 = 0.f, l1 = 0.f;

    const int row0g = q0 + warp * 16 + gg;
    const int row1g = row0g + 8;

    for (int kt = 0; kt < ktiles; kt++) {
        const int kbase = kt * 32;
        const unsigned* Ks = sm + ((kt & 1) ? AKS1 : AKS0);
        const unsigned* Vs = sm + ((kt & 1) ? AVS1 : AVS0);

        if (kt + 1 < ktiles) {
            unsigned* kd = sm + (((kt + 1) & 1) ? AKS1 : AKS0);
            unsigned* vd = sm + (((kt + 1) & 1) ? AVS1 : AVS0);
            const size_t nb = base + (size_t)(kbase + 32) * 64;
#pragma unroll
            for (int i = 0; i < 4; i++) {
                int idx = i * 128 + tid;
                int r = idx >> 4, c4 = (idx & 15) * 4;
                cp_async16(kd + r * STK + c4, k + nb + (size_t)r * 64 + c4);
                cp_async16(vd + r * STV + c4, v + nb + (size_t)r * 64 + c4);
            }
            CP_COMMIT();
        }

        float s[4][4];
#pragma unroll
        for (int nt = 0; nt < 4; nt++)
#pragma unroll
            for (int r = 0; r < 4; r++) s[nt][r] = 0.f;
#pragma unroll
        for (int ks = 0; ks < 8; ks++) {
            unsigned bf[4][2];
#pragma unroll
            for (int nt = 0; nt < 4; nt++) {
                bf[nt][0] = Ks[(nt * 8 + gg) * STK + ks * 8 + qq];
                bf[nt][1] = Ks[(nt * 8 + gg) * STK + ks * 8 + qq + 4];
            }
#pragma unroll
            for (int nt = 0; nt < 4; nt++) mma8(s[nt], qf[ks], bf[nt]);
        }

        if (kt >= 2 * qt) {
#pragma unroll
            for (int nt = 0; nt < 4; nt++) {
                int c0 = kbase + nt * 8 + 2 * qq;
                if (c0 > row0g)     s[nt][0] = -1e30f;
                if (c0 + 1 > row0g) s[nt][1] = -1e30f;
                if (c0 > row1g)     s[nt][2] = -1e30f;
                if (c0 + 1 > row1g) s[nt][3] = -1e30f;
            }
        }

        float rm0 = -1e30f, rm1 = -1e30f;
#pragma unroll
        for (int nt = 0; nt < 4; nt++) {
            rm0 = fmaxf(rm0, fmaxf(s[nt][0], s[nt][1]));
            rm1 = fmaxf(rm1, fmaxf(s[nt][2], s[nt][3]));
        }
        rm0 = fmaxf(rm0, __shfl_xor_sync(0xffffffffu, rm0, 1));
        rm0 = fmaxf(rm0, __shfl_xor_sync(0xffffffffu, rm0, 2));
        rm1 = fmaxf(rm1, __shfl_xor_sync(0xffffffffu, rm1, 1));
        rm1 = fmaxf(rm1, __shfl_xor_sync(0xffffffffu, rm1, 2));
        float nm0 = fmaxf(m0, rm0), nm1 = fmaxf(m1, rm1);
        float corr0 = __expf(m0 - nm0), corr1 = __expf(m1 - nm1);
        float rs0 = 0.f, rs1 = 0.f;
#pragma unroll
        for (int nt = 0; nt < 4; nt++) {
            s[nt][0] = __expf(s[nt][0] - nm0);
            s[nt][1] = __expf(s[nt][1] - nm0);
            s[nt][2] = __expf(s[nt][2] - nm1);
            s[nt][3] = __expf(s[nt][3] - nm1);
            rs0 += s[nt][0] + s[nt][1];
            rs1 += s[nt][2] + s[nt][3];
        }
        rs0 += __shfl_xor_sync(0xffffffffu, rs0, 1);
        rs0 += __shfl_xor_sync(0xffffffffu, rs0, 2);
        rs1 += __shfl_xor_sync(0xffffffffu, rs1, 1);
        rs1 += __shfl_xor_sync(0xffffffffu, rs1, 2);
        l0 = l0 * corr0 + rs0;
        l1 = l1 * corr1 + rs1;
        m0 = nm0; m1 = nm1;
#pragma unroll
        for (int nt = 0; nt < 8; nt++) {
            oacc[nt][0] *= corr0; oacc[nt][1] *= corr0;
            oacc[nt][2] *= corr1; oacc[nt][3] *= corr1;
        }

        {
            unsigned* pr = Ps + (warp * 16 + gg) * STP;
#pragma unroll
            for (int nt = 0; nt < 4; nt++) {
                *(uint2*)(pr + nt * 8 + 2 * qq) = make_uint2(f2tf(s[nt][0]), f2tf(s[nt][1]));
                *(uint2*)(pr + 8 * STP + nt * 8 + 2 * qq) = make_uint2(f2tf(s[nt][2]), f2tf(s[nt][3]));
            }
        }
        __syncwarp();

#pragma unroll
        for (int ks = 0; ks < 4; ks++) {
            unsigned af[4];
            const unsigned* pr = Ps + (warp * 16 + gg) * STP + ks * 8;
            af[0] = pr[qq];
            af[1] = pr[8 * STP + qq];
            af[2] = pr[qq + 4];
            af[3] = pr[8 * STP + qq + 4];
#pragma unroll
            for (int nt = 0; nt < 8; nt++) {
                unsigned bf2[2];
                bf2[0] = Vs[(ks * 8 + qq) * STV + nt * 8 + gg];
                bf2[1] = Vs[(ks * 8 + qq + 4) * STV + nt * 8 + gg];
                mma8(oacc[nt], af, bf2);
            }
        }

        if (kt + 1 < ktiles) {
            CP_WAIT0();
            __syncthreads();
        }
    }

    const float inv0 = 1.f / l0, inv1 = 1.f / l1;
    const int b = bh / Hn, h = bh % Hn;
    __half* p0 = o + ((size_t)(b * Tn + row0g)) * Cn + h * 64;
    __half* p1 = o + ((size_t)(b * Tn + row1g)) * Cn + h * 64;
#pragma unroll
    for (int nt = 0; nt < 8; nt++) {
        *(__half2*)(p0 + nt * 8 + 2 * qq) = __floats2half2_rn(oacc[nt][0] * inv0, oacc[nt][1] * inv0);
        *(__half2*)(p1 + nt * 8 + 2 * qq) = __floats2half2_rn(oacc[nt][2] * inv1, oacc[nt][3] * inv1);
    }
}

// ---------------- fused residual + LayerNorm (fp32 out + optional fp16 out) -------
__global__ __launch_bounds__(128) void ln_res_k(
    const float* __restrict__ x, const float* __restrict__ y,
    const float* __restrict__ g, const float* __restrict__ bb,
    float* __restrict__ out, __half* __restrict__ out16)
{
    __shared__ float red[4];
    const int row = blockIdx.x;
    const int tid = threadIdx.x;
    const size_t base = (size_t)row * Cn;
    float v0 = x[base + tid]       + y[base + tid];
    float v1 = x[base + tid + 128] + y[base + tid + 128];
    float v2 = x[base + tid + 256] + y[base + tid + 256];

    float s = v0 + v1 + v2;
    for (int o = 16; o > 0; o >>= 1) s += __shfl_xor_sync(0xffffffffu, s, o);
    if ((tid & 31) == 0) red[tid >> 5] = s;
    __syncthreads();
    float mean = (red[0] + red[1] + red[2] + red[3]) * (1.f / Cn);
    __syncthreads();

    float d0 = v0 - mean, d1 = v1 - mean, d2 = v2 - mean;
    float sq = d0 * d0 + d1 * d1 + d2 * d2;
    for (int o = 16; o > 0; o >>= 1) sq += __shfl_xor_sync(0xffffffffu, sq, o);
    if ((tid & 31) == 0) red[tid >> 5] = sq;
    __syncthreads();
    float var = (red[0] + red[1] + red[2] + red[3]) * (1.f / Cn);
    float inv = rsqrtf(var + EPSn);

    float o0 = g[tid]       * d0 * inv + bb[tid];
    float o1 = g[tid + 128] * d1 * inv + bb[tid + 128];
    float o2 = g[tid + 256] * d2 * inv + bb[tid + 256];
    out[base + tid]       = o0;
    out[base + tid + 128] = o1;
    out[base + tid + 256] = o2;
    if (out16) {
        out16[base + tid]       = __float2half(o0);
        out16[base + tid + 128] = __float2half(o1);
        out16[base + tid + 256] = __float2half(o2);
    }
}

// ---------------- host orchestration ----------------
extern "C" void kernel_launch(void* const* d_in, const int* in_sizes, int n_in,
                              void* d_out, int out_size)
{
    (void)in_sizes; (void)n_in; (void)out_size;
    const float* x    = (const float*)d_in[0];
    const float* q1w  = (const float*)d_in[1];
    const float* q1b  = (const float*)d_in[2];
    const float* k1w  = (const float*)d_in[3];
    const float* k1b  = (const float*)d_in[4];
    const float* v1w  = (const float*)d_in[5];
    const float* v1b  = (const float*)d_in[6];
    const float* p1w  = (const float*)d_in[7];
    const float* p1b  = (const float*)d_in[8];
    const float* ln1g = (const float*)d_in[9];
    const float* ln1b = (const float*)d_in[10];
    const float* q2w  = (const float*)d_in[11];
    const float* q2b  = (const float*)d_in[12];
    const float* k2w  = (const float*)d_in[13];
    const float* k2b  = (const float*)d_in[14];
    const float* v2w  = (const float*)d_in[15];
    const float* v2b  = (const float*)d_in[16];
    const float* p2w  = (const float*)d_in[17];
    const float* p2b  = (const float*)d_in[18];
    const float* ln2g = (const float*)d_in[19];
    const float* ln2b = (const float*)d_in[20];
    const float* f1w  = (const float*)d_in[21];
    const float* f1b  = (const float*)d_in[22];
    const float* f2w  = (const float*)d_in[23];
    const float* f2b  = (const float*)d_in[24];
    const float* ln3g = (const float*)d_in[25];
    const float* ln3b = (const float*)d_in[26];
    float* out = (float*)d_out;

    __half *pwqkv, *pwp, *pwf1, *pwf2, *px16, *po16, *pr16, *ph16;
    float *pbqkv, *pq, *pk, *pv, *pp, *pr1, *pr2;
    cudaGetSymbolAddress((void**)&pwqkv, g_wqkv16);
    cudaGetSymbolAddress((void**)&pwp,  g_wp16);
    cudaGetSymbolAddress((void**)&pwf1, g_wf1t);
    cudaGetSymbolAddress((void**)&pwf2, g_wf2t);
    cudaGetSymbolAddress((void**)&px16, g_x16);
    cudaGetSymbolAddress((void**)&po16, g_o16);
    cudaGetSymbolAddress((void**)&pr16, g_r16);
    cudaGetSymbolAddress((void**)&ph16, g_h16);
    cudaGetSymbolAddress((void**)&pbqkv, g_bqkv);
    cudaGetSymbolAddress((void**)&pq,  g_q);
    cudaGetSymbolAddress((void**)&pk,  g_k);
    cudaGetSymbolAddress((void**)&pv,  g_v);
    cudaGetSymbolAddress((void**)&pp,  g_p);
    cudaGetSymbolAddress((void**)&pr1, g_r1);
    cudaGetSymbolAddress((void**)&pr2, g_r2);

    // one-time converts / packs
    f2h_k<<<(BTn * Cn + 255) / 256, 256>>>(x, px16, BTn * Cn);
    wt_pack16<<<(FFn * Cn + 255) / 256, 256>>>(f1w, pwf1, FFn, Cn);
    wt_pack16<<<(Cn * FFn + 255) / 256, 256>>>(f2w, pwf2, Cn, FFn);

    auto run_layer = [&](const float* xin_f32, const __half* xin_f16,
                         const float* qw, const float* qb,
                         const float* kw, const float* kb,
                         const float* vw, const float* vb,
                         const float* pw, const float* pb,
                         const float* lng, const float* lnb,
                         float* rout, __half* rout16) {
        qkv_pack_w16<<<(3 * Cn * Cn + 255) / 256, 256>>>(qw, kw, vw, pwqkv);
        qkv_pack_b<<<(3 * Cn + 255) / 256, 256>>>(qb, kb, vb, pbqkv);
        wt_pack16<<<(Cn * Cn + 255) / 256, 256>>>(pw, pwp, Cn, Cn);
        gemm_f16<<<dim3(3 * Cn / 128, BTn / 128), 256>>>(
            xin_f16, pwqkv, pbqkv, nullptr, nullptr, BTn, 3 * Cn, Cn, 2, pq, pk, pv);
        attn_mma<<<dim3(Tn / 64, Bn * Hn), 128>>>(pq, pk, pv, po16);
        gemm_f16<<<dim3(Cn / 128, BTn / 128), 256>>>(
            po16, pwp, pb, pp, nullptr, BTn, Cn, Cn, 0, nullptr, nullptr, nullptr);
        ln_res_k<<<BTn, 128>>>(xin_f32, pp, lng, lnb, rout, rout16);
    };

    run_layer(x,   px16, q1w, q1b, k1w, k1b, v1w, v1b, p1w, p1b, ln1g, ln1b, pr1, pr16);
    run_layer(pr1, pr16, q2w, q2b, k2w, k2b, v2w, v2b, p2w, p2b, ln2g, ln2b, pr2, pr16);

    gemm_f16<<<dim3(FFn / 128, BTn / 128), 256>>>(
        pr16, pwf1, f1b, nullptr, ph16, BTn, FFn, Cn, 1, nullptr, nullptr, nullptr);
    gemm_f16<<<dim3(Cn / 128, BTn / 128), 256>>>(
        ph16, pwf2, f2b, pp, nullptr, BTn, Cn, FFn, 0, nullptr, nullptr, nullptr);
    ln_res_k<<<BTn, 128>>>(pr2, pp, ln3g, ln3b, out, nullptr);
}

// round 8
// speedup vs baseline: 1.9044x; 1.1081x over previous
#include <cuda_runtime.h>
#include <cuda_fp16.h>
#include <math.h>

#define Bn 64
#define Tn 512
#define Cn 384
#define Hn 6
#define HDn 64
#define FFn 1536
#define BTn (Bn*Tn)
#define EPSn 1e-5f

// fp16 gemm smem stride (u32 words per row of 32 halves + pad)
#define SWS 20

// fp16 attention smem (u32 word strides)
#define STKW 36   // K row (key): 72 halves
#define STVW 20   // Vt row (d): 40 halves
#define BKS0 0
#define BVS0 (32*STKW)
#define BKS1 (BVS0 + 64*STVW)
#define BVS1 (BKS1 + 32*STKW)
#define BTOT (BVS1 + 64*STVW)

// ---------------- scratch ----------------
__device__ __half g_wqkv16[3*Cn*Cn];     // [n=3C][k=C]
__device__ __half g_wp16[Cn*Cn];         // [n][k]
__device__ __half g_wf1t[FFn*Cn];        // [n=FF][k=C]
__device__ __half g_wf2t[Cn*FFn];        // [n=C][k=FF]
__device__ float  g_bqkv[3*Cn];
__device__ __half g_x16[(size_t)BTn*Cn];
__device__ __half g_o16[(size_t)BTn*Cn];
__device__ __half g_r16[(size_t)BTn*Cn];
__device__ __half g_h16[(size_t)BTn*FFn];
__device__ __half g_q16[(size_t)Bn*Hn*Tn*HDn];   // [bh][t][d], pre-scaled
__device__ __half g_k16[(size_t)Bn*Hn*Tn*HDn];   // [bh][t][d]
__device__ __half g_v16t[(size_t)Bn*Hn*HDn*Tn];  // [bh][d][t]
__device__ float g_p[(size_t)BTn*Cn];
__device__ float g_r1[(size_t)BTn*Cn];
__device__ float g_r2[(size_t)BTn*Cn];

// ---------------- packs ----------------
__global__ void qkv_pack_w16(const float* __restrict__ qw, const float* __restrict__ kw,
                             const float* __restrict__ vw, __half* __restrict__ o) {
    int idx = blockIdx.x * blockDim.x + threadIdx.x;
    if (idx >= 3 * Cn * Cn) return;
    int n = idx / Cn;
    int k = idx % Cn;
    int mat = n / Cn;
    int local = n % Cn;
    int h = local >> 6, d = local & 63;
    const float* w = (mat == 0) ? qw : (mat == 1) ? kw : vw;
    o[idx] = __float2half(w[((size_t)h * Cn + k) * HDn + d]);
}
__global__ void qkv_pack_b(const float* __restrict__ qb, const float* __restrict__ kb,
                           const float* __restrict__ vb, float* __restrict__ o) {
    int i = threadIdx.x + blockIdx.x * blockDim.x;
    if (i >= 3 * Cn) return;
    const float* b = (i < Cn) ? qb : (i < 2 * Cn) ? kb : vb;
    o[i] = b[i % Cn];
}
__global__ void wt_pack16(const float* __restrict__ w, __half* __restrict__ o, int N, int K) {
    int idx = blockIdx.x * blockDim.x + threadIdx.x;
    if (idx >= N * K) return;
    int n = idx / K, k = idx % K;
    o[idx] = __float2half(w[(size_t)k * N + n]);
}
__global__ void f2h_k(const float* __restrict__ a, __half* __restrict__ o, int n) {
    int i = blockIdx.x * blockDim.x + threadIdx.x;
    if (i < n) o[i] = __float2half(a[i]);
}

// ---------------- mma / async helpers ----------------
__device__ __forceinline__ void mma16(float* d, const unsigned* a, const unsigned* b) {
    asm("mma.sync.aligned.m16n8k16.row.col.f32.f16.f16.f32 "
        "{%0,%1,%2,%3},{%4,%5,%6,%7},{%8,%9},{%0,%1,%2,%3};"
        : "+f"(d[0]), "+f"(d[1]), "+f"(d[2]), "+f"(d[3])
        : "r"(a[0]), "r"(a[1]), "r"(a[2]), "r"(a[3]), "r"(b[0]), "r"(b[1]));
}
__device__ __forceinline__ unsigned h2u(float a, float b) {
    __half2 h = __floats2half2_rn(a, b);
    return *(unsigned*)&h;
}
__device__ __forceinline__ void cp_async16(void* smem_dst, const void* gsrc) {
    unsigned saddr = (unsigned)__cvta_generic_to_shared(smem_dst);
    asm volatile("cp.async.ca.shared.global [%0], [%1], 16;\n" :: "r"(saddr), "l"(gsrc));
}
#define CP_COMMIT() asm volatile("cp.async.commit_group;\n" ::: "memory")
#define CP_WAIT1()  asm volatile("cp.async.wait_group 1;\n" ::: "memory")
#define CP_WAIT0()  asm volatile("cp.async.wait_group 0;\n" ::: "memory")

// ---------------- fp16 GEMM (unchanged core from R7) ----------------------------
// flags: 0 = fp32 out; 1 = relu + fp16 out; 2 = qkv scatter fp16 (+rope, q scaled)
__global__ __launch_bounds__(256) void gemm_f16(
    const __half* __restrict__ A, const __half* __restrict__ Bm,
    const float* __restrict__ bias, float* __restrict__ Cout,
    __half* __restrict__ Cout16,
    int M, int N, int K, int flags,
    __half* __restrict__ oq, __half* __restrict__ ok, __half* __restrict__ ov)
{
    __shared__ __align__(16) unsigned As[3][128 * SWS];
    __shared__ __align__(16) unsigned Bs[3][128 * SWS];

    const int tid = threadIdx.x;
    const int lane = tid & 31, warp = tid >> 5;
    const int warpM = warp >> 2, warpN = warp & 3;
    const int bm = blockIdx.y * 128, bn = blockIdx.x * 128;
    const int qq = lane & 3, gg = lane >> 2;

    const int sRow = tid >> 1;
    const int sOff = (tid & 1) * 8;
    const __half* Ap = A + (size_t)(bm + sRow) * K + (tid & 1) * 16;
    const __half* Bp = Bm + (size_t)(bn + sRow) * K + (tid & 1) * 16;

    float acc[4][4][4];
#pragma unroll
    for (int i = 0; i < 4; i++)
#pragma unroll
        for (int j = 0; j < 4; j++)
#pragma unroll
            for (int r = 0; r < 4; r++) acc[i][j][r] = 0.f;

    const int KT = K >> 5;

    {
        unsigned* as = As[0]; unsigned* bs = Bs[0];
        cp_async16(as + sRow * SWS + sOff,     Ap);
        cp_async16(as + sRow * SWS + sOff + 4, Ap + 8);
        cp_async16(bs + sRow * SWS + sOff,     Bp);
        cp_async16(bs + sRow * SWS + sOff + 4, Bp + 8);
    }
    CP_COMMIT();
    {
        unsigned* as = As[1]; unsigned* bs = Bs[1];
        cp_async16(as + sRow * SWS + sOff,     Ap + 32);
        cp_async16(as + sRow * SWS + sOff + 4, Ap + 40);
        cp_async16(bs + sRow * SWS + sOff,     Bp + 32);
        cp_async16(bs + sRow * SWS + sOff + 4, Bp + 40);
    }
    CP_COMMIT();

    for (int kt = 0; kt < KT; kt++) {
        CP_WAIT1();
        __syncthreads();

        if (kt + 2 < KT) {
            int st = (kt + 2) % 3;
            unsigned* as = As[st]; unsigned* bs = Bs[st];
            const __half* ap = Ap + (size_t)(kt + 2) * 32;
            const __half* bp = Bp + (size_t)(kt + 2) * 32;
            cp_async16(as + sRow * SWS + sOff,     ap);
            cp_async16(as + sRow * SWS + sOff + 4, ap + 8);
            cp_async16(bs + sRow * SWS + sOff,     bp);
            cp_async16(bs + sRow * SWS + sOff + 4, bp + 8);
        }
        CP_COMMIT();

        const unsigned* as = As[kt % 3];
        const unsigned* bs = Bs[kt % 3];
#pragma unroll
        for (int ko = 0; ko < 16; ko += 8) {
            unsigned af[4][4], bf[4][2];
#pragma unroll
            for (int mi = 0; mi < 4; mi++) {
                int m0 = warpM * 64 + mi * 16 + gg;
                af[mi][0] = as[(m0)     * SWS + ko + qq];
                af[mi][1] = as[(m0 + 8) * SWS + ko + qq];
                af[mi][2] = as[(m0)     * SWS + ko + qq + 4];
                af[mi][3] = as[(m0 + 8) * SWS + ko + qq + 4];
            }
#pragma unroll
            for (int ni = 0; ni < 4; ni++) {
                int n0 = warpN * 32 + ni * 8 + gg;
                bf[ni][0] = bs[(n0) * SWS + ko + qq];
                bf[ni][1] = bs[(n0) * SWS + ko + qq + 4];
            }
#pragma unroll
            for (int mi = 0; mi < 4; mi++)
#pragma unroll
                for (int ni = 0; ni < 4; ni++)
                    mma16(acc[mi][ni], af[mi], bf[ni]);
        }
    }

    const float scale = 0.051031036307982884f;   // 1/sqrt(384)
#pragma unroll
    for (int mi = 0; mi < 4; mi++) {
        int row0 = bm + warpM * 64 + mi * 16 + gg;
        float sn[2], cs[2];
        if (flags == 2) {
            sincosf((float)(row0 & 511), &sn[0], &cs[0]);
            sincosf((float)((row0 + 8) & 511), &sn[1], &cs[1]);
        }
#pragma unroll
        for (int ni = 0; ni < 4; ni++) {
            int col = bn + warpN * 32 + ni * 8 + qq * 2;
            float b0 = bias[col], b1 = bias[col + 1];
#pragma unroll
            for (int half = 0; half < 2; half++) {
                int row = row0 + half * 8;
                float xr = acc[mi][ni][half * 2 + 0] + b0;
                float xi = acc[mi][ni][half * 2 + 1] + b1;
                if (flags == 2) {
                    int mat = col / Cn;
                    if (mat < 2) {
                        float nr = cs[half] * xr - sn[half] * xi;
                        float ni2 = sn[half] * xr + cs[half] * xi;
                        xr = nr; xi = ni2;
                    }
                    int local = col - mat * Cn;
                    int h = local >> 6, d = local & 63;
                    int bb = row >> 9, t = row & 511;
                    if (mat == 0) {
                        __half2 hv = __floats2half2_rn(xr * scale, xi * scale);
                        *(__half2*)(oq + ((size_t)(bb * Hn + h) * Tn + t) * HDn + d) = hv;
                    } else if (mat == 1) {
                        __half2 hv = __floats2half2_rn(xr, xi);
                        *(__half2*)(ok + ((size_t)(bb * Hn + h) * Tn + t) * HDn + d) = hv;
                    } else {
                        // V transposed: [bh][d][t]
                        size_t vb = ((size_t)(bb * Hn + h) * HDn + d) * Tn + t;
                        ov[vb]      = __float2half(xr);
                        ov[vb + Tn] = __float2half(xi);
                    }
                } else if (flags == 1) {
                    xr = fmaxf(xr, 0.f); xi = fmaxf(xi, 0.f);
                    __half2* p = (__half2*)(Cout16 + (size_t)row * N + col);
                    *p = __floats2half2_rn(xr, xi);
                } else {
                    float2* p = (float2*)(Cout + (size_t)row * N + col);
                    *p = make_float2(xr, xi);
                }
            }
        }
    }
}

// ---------------- fp16 tensor-core causal flash attention -------------------------
// q [bh][t][d] pre-scaled fp16; k [bh][t][d] fp16; v [bh][d][t] fp16
__global__ __launch_bounds__(128) void attn_mma(
    const __half* __restrict__ q, const __half* __restrict__ k,
    const __half* __restrict__ v, __half* __restrict__ o)
{
    __shared__ __align__(16) unsigned sm[BTOT];

    const int bh = blockIdx.y;
    const int qt = gridDim.x - 1 - blockIdx.x;   // long blocks first
    const int tid = threadIdx.x;
    const int warp = tid >> 5, lane = tid & 31;
    const int gg = lane >> 2, qq = lane & 3;
    const size_t base = (size_t)bh * Tn * HDn;   // same element count for q/k/v
    const int q0 = qt * 64;
    const int ktiles = 2 * qt + 2;

    // prefetch KV tile 0
    {
        unsigned* kd = sm + BKS0;
        unsigned* vd = sm + BVS0;
#pragma unroll
        for (int i = 0; i < 2; i++) {
            int idx = i * 128 + tid;                 // 256 K-segments
            int r = idx >> 3, seg = idx & 7;
            cp_async16(kd + r * STKW + seg * 4, k + base + (size_t)r * 64 + seg * 8);
            int rv = idx >> 2, sv = idx & 3;         // 256 Vt-segments
            cp_async16(vd + rv * STVW + sv * 4, v + base + (size_t)rv * Tn + sv * 8);
        }
        CP_COMMIT();
    }

    // Q A-fragments direct from global (fp16, pre-scaled)
    unsigned qf[4][4];
    {
        const __half* q0p = q + base + (size_t)(q0 + warp * 16 + gg) * 64;
        const __half* q1p = q0p + 8 * 64;
#pragma unroll
        for (int ks = 0; ks < 4; ks++) {
            qf[ks][0] = *(const unsigned*)(q0p + ks * 16 + 2 * qq);
            qf[ks][1] = *(const unsigned*)(q1p + ks * 16 + 2 * qq);
            qf[ks][2] = *(const unsigned*)(q0p + ks * 16 + 2 * qq + 8);
            qf[ks][3] = *(const unsigned*)(q1p + ks * 16 + 2 * qq + 8);
        }
    }
    CP_WAIT0();
    __syncthreads();

    float oacc[8][4];
#pragma unroll
    for (int i = 0; i < 8; i++)
#pragma unroll
        for (int r = 0; r < 4; r++) oacc[i][r] = 0.f;
    float m0 = -INFINITY, m1 = -INFINITY, l0 = 0.f, l1 = 0.f;

    const int row0g = q0 + warp * 16 + gg;
    const int row1g = row0g + 8;

    for (int kt = 0; kt < ktiles; kt++) {
        const int kbase = kt * 32;
        const unsigned* Ks = sm + ((kt & 1) ? BKS1 : BKS0);
        const unsigned* Vs = sm + ((kt & 1) ? BVS1 : BVS0);

        if (kt + 1 < ktiles) {
            unsigned* kd = sm + (((kt + 1) & 1) ? BKS1 : BKS0);
            unsigned* vd = sm + (((kt + 1) & 1) ? BVS1 : BVS0);
#pragma unroll
            for (int i = 0; i < 2; i++) {
                int idx = i * 128 + tid;
                int r = idx >> 3, seg = idx & 7;
                cp_async16(kd + r * STKW + seg * 4,
                           k + base + (size_t)(kbase + 32 + r) * 64 + seg * 8);
                int rv = idx >> 2, sv = idx & 3;
                cp_async16(vd + rv * STVW + sv * 4,
                           v + base + (size_t)rv * Tn + kbase + 32 + sv * 8);
            }
            CP_COMMIT();
        }

        // S = Q K^T : 4 k16 steps over d=64, 4 n-tiles of 8 keys
        float s[4][4];
#pragma unroll
        for (int nt = 0; nt < 4; nt++)
#pragma unroll
            for (int r = 0; r < 4; r++) s[nt][r] = 0.f;
#pragma unroll
        for (int ks = 0; ks < 4; ks++) {
            unsigned bf[4][2];
#pragma unroll
            for (int nt = 0; nt < 4; nt++) {
                bf[nt][0] = Ks[(nt * 8 + gg) * STKW + ks * 8 + qq];
                bf[nt][1] = Ks[(nt * 8 + gg) * STKW + ks * 8 + qq + 4];
            }
#pragma unroll
            for (int nt = 0; nt < 4; nt++) mma16(s[nt], qf[ks], bf[nt]);
        }

        // causal mask (diagonal 64-key block only)
        if (kt >= 2 * qt) {
#pragma unroll
            for (int nt = 0; nt < 4; nt++) {
                int c0 = kbase + nt * 8 + 2 * qq;
                if (c0 > row0g)     s[nt][0] = -1e30f;
                if (c0 + 1 > row0g) s[nt][1] = -1e30f;
                if (c0 > row1g)     s[nt][2] = -1e30f;
                if (c0 + 1 > row1g) s[nt][3] = -1e30f;
            }
        }

        // online softmax
        float rm0 = -1e30f, rm1 = -1e30f;
#pragma unroll
        for (int nt = 0; nt < 4; nt++) {
            rm0 = fmaxf(rm0, fmaxf(s[nt][0], s[nt][1]));
            rm1 = fmaxf(rm1, fmaxf(s[nt][2], s[nt][3]));
        }
        rm0 = fmaxf(rm0, __shfl_xor_sync(0xffffffffu, rm0, 1));
        rm0 = fmaxf(rm0, __shfl_xor_sync(0xffffffffu, rm0, 2));
        rm1 = fmaxf(rm1, __shfl_xor_sync(0xffffffffu, rm1, 1));
        rm1 = fmaxf(rm1, __shfl_xor_sync(0xffffffffu, rm1, 2));
        float nm0 = fmaxf(m0, rm0), nm1 = fmaxf(m1, rm1);
        float corr0 = __expf(m0 - nm0), corr1 = __expf(m1 - nm1);
        float rs0 = 0.f, rs1 = 0.f;
#pragma unroll
        for (int nt = 0; nt < 4; nt++) {
            s[nt][0] = __expf(s[nt][0] - nm0);
            s[nt][1] = __expf(s[nt][1] - nm0);
            s[nt][2] = __expf(s[nt][2] - nm1);
            s[nt][3] = __expf(s[nt][3] - nm1);
            rs0 += s[nt][0] + s[nt][1];
            rs1 += s[nt][2] + s[nt][3];
        }
        rs0 += __shfl_xor_sync(0xffffffffu, rs0, 1);
        rs0 += __shfl_xor_sync(0xffffffffu, rs0, 2);
        rs1 += __shfl_xor_sync(0xffffffffu, rs1, 1);
        rs1 += __shfl_xor_sync(0xffffffffu, rs1, 2);
        l0 = l0 * corr0 + rs0;
        l1 = l1 * corr1 + rs1;
        m0 = nm0; m1 = nm1;
#pragma unroll
        for (int nt = 0; nt < 8; nt++) {
            oacc[nt][0] *= corr0; oacc[nt][1] *= corr0;
            oacc[nt][2] *= corr1; oacc[nt][3] *= corr1;
        }

        // P C-fragment packs directly into m16n8k16 A-fragments (no smem round trip)
        unsigned pa[2][4];
        pa[0][0] = h2u(s[0][0], s[0][1]);
        pa[0][1] = h2u(s[0][2], s[0][3]);
        pa[0][2] = h2u(s[1][0], s[1][1]);
        pa[0][3] = h2u(s[1][2], s[1][3]);
        pa[1][0] = h2u(s[2][0], s[2][1]);
        pa[1][1] = h2u(s[2][2], s[2][3]);
        pa[1][2] = h2u(s[3][0], s[3][1]);
        pa[1][3] = h2u(s[3][2], s[3][3]);

        // O += P V : 2 k16 steps over 32 keys, 8 n-tiles of 8 d
#pragma unroll
        for (int ks = 0; ks < 2; ks++) {
#pragma unroll
            for (int nt = 0; nt < 8; nt++) {
                unsigned bf2[2];
                bf2[0] = Vs[(nt * 8 + gg) * STVW + ks * 8 + qq];
                bf2[1] = Vs[(nt * 8 + gg) * STVW + ks * 8 + qq + 4];
                mma16(oacc[nt], pa[ks], bf2);
            }
        }

        if (kt + 1 < ktiles) {
            CP_WAIT0();
            __syncthreads();
        }
    }

    // epilogue: normalize, fp16 out to [BT][C]
    const float inv0 = 1.f / l0, inv1 = 1.f / l1;
    const int b = bh / Hn, h = bh % Hn;
    __half* p0 = o + ((size_t)(b * Tn + row0g)) * Cn + h * 64;
    __half* p1 = o + ((size_t)(b * Tn + row1g)) * Cn + h * 64;
#pragma unroll
    for (int nt = 0; nt < 8; nt++) {
        *(__half2*)(p0 + nt * 8 + 2 * qq) = __floats2half2_rn(oacc[nt][0] * inv0, oacc[nt][1] * inv0);
        *(__half2*)(p1 + nt * 8 + 2 * qq) = __floats2half2_rn(oacc[nt][2] * inv1, oacc[nt][3] * inv1);
    }
}

// ---------------- fused residual + LayerNorm (fp32 out + optional fp16 out) -------
__global__ __launch_bounds__(128) void ln_res_k(
    const float* __restrict__ x, const float* __restrict__ y,
    const float* __restrict__ g, const float* __restrict__ bb,
    float* __restrict__ out, __half* __restrict__ out16)
{
    __shared__ float red[4];
    const int row = blockIdx.x;
    const int tid = threadIdx.x;
    const size_t base = (size_t)row * Cn;
    float v0 = x[base + tid]       + y[base + tid];
    float v1 = x[base + tid + 128] + y[base + tid + 128];
    float v2 = x[base + tid + 256] + y[base + tid + 256];

    float s = v0 + v1 + v2;
    for (int o = 16; o > 0; o >>= 1) s += __shfl_xor_sync(0xffffffffu, s, o);
    if ((tid & 31) == 0) red[tid >> 5] = s;
    __syncthreads();
    float mean = (red[0] + red[1] + red[2] + red[3]) * (1.f / Cn);
    __syncthreads();

    float d0 = v0 - mean, d1 = v1 - mean, d2 = v2 - mean;
    float sq = d0 * d0 + d1 * d1 + d2 * d2;
    for (int o = 16; o > 0; o >>= 1) sq += __shfl_xor_sync(0xffffffffu, sq, o);
    if ((tid & 31) == 0) red[tid >> 5] = sq;
    __syncthreads();
    float var = (red[0] + red[1] + red[2] + red[3]) * (1.f / Cn);
    float inv = rsqrtf(var + EPSn);

    float o0 = g[tid]       * d0 * inv + bb[tid];
    float o1 = g[tid + 128] * d1 * inv + bb[tid + 128];
    float o2 = g[tid + 256] * d2 * inv + bb[tid + 256];
    out[base + tid]       = o0;
    out[base + tid + 128] = o1;
    out[base + tid + 256] = o2;
    if (out16) {
        out16[base + tid]       = __float2half(o0);
        out16[base + tid + 128] = __float2half(o1);
        out16[base + tid + 256] = __float2half(o2);
    }
}

// ---------------- host orchestration ----------------
extern "C" void kernel_launch(void* const* d_in, const int* in_sizes, int n_in,
                              void* d_out, int out_size)
{
    (void)in_sizes; (void)n_in; (void)out_size;
    const float* x    = (const float*)d_in[0];
    const float* q1w  = (const float*)d_in[1];
    const float* q1b  = (const float*)d_in[2];
    const float* k1w  = (const float*)d_in[3];
    const float* k1b  = (const float*)d_in[4];
    const float* v1w  = (const float*)d_in[5];
    const float* v1b  = (const float*)d_in[6];
    const float* p1w  = (const float*)d_in[7];
    const float* p1b  = (const float*)d_in[8];
    const float* ln1g = (const float*)d_in[9];
    const float* ln1b = (const float*)d_in[10];
    const float* q2w  = (const float*)d_in[11];
    const float* q2b  = (const float*)d_in[12];
    const float* k2w  = (const float*)d_in[13];
    const float* k2b  = (const float*)d_in[14];
    const float* v2w  = (const float*)d_in[15];
    const float* v2b  = (const float*)d_in[16];
    const float* p2w  = (const float*)d_in[17];
    const float* p2b  = (const float*)d_in[18];
    const float* ln2g = (const float*)d_in[19];
    const float* ln2b = (const float*)d_in[20];
    const float* f1w  = (const float*)d_in[21];
    const float* f1b  = (const float*)d_in[22];
    const float* f2w  = (const float*)d_in[23];
    const float* f2b  = (const float*)d_in[24];
    const float* ln3g = (const float*)d_in[25];
    const float* ln3b = (const float*)d_in[26];
    float* out = (float*)d_out;

    __half *pwqkv, *pwp, *pwf1, *pwf2, *px16, *po16, *pr16, *ph16, *pq16, *pk16, *pv16t;
    float *pbqkv, *pp, *pr1, *pr2;
    cudaGetSymbolAddress((void**)&pwqkv, g_wqkv16);
    cudaGetSymbolAddress((void**)&pwp,  g_wp16);
    cudaGetSymbolAddress((void**)&pwf1, g_wf1t);
    cudaGetSymbolAddress((void**)&pwf2, g_wf2t);
    cudaGetSymbolAddress((void**)&px16, g_x16);
    cudaGetSymbolAddress((void**)&po16, g_o16);
    cudaGetSymbolAddress((void**)&pr16, g_r16);
    cudaGetSymbolAddress((void**)&ph16, g_h16);
    cudaGetSymbolAddress((void**)&pq16, g_q16);
    cudaGetSymbolAddress((void**)&pk16, g_k16);
    cudaGetSymbolAddress((void**)&pv16t, g_v16t);
    cudaGetSymbolAddress((void**)&pbqkv, g_bqkv);
    cudaGetSymbolAddress((void**)&pp,  g_p);
    cudaGetSymbolAddress((void**)&pr1, g_r1);
    cudaGetSymbolAddress((void**)&pr2, g_r2);

    f2h_k<<<(BTn * Cn + 255) / 256, 256>>>(x, px16, BTn * Cn);
    wt_pack16<<<(FFn * Cn + 255) / 256, 256>>>(f1w, pwf1, FFn, Cn);
    wt_pack16<<<(Cn * FFn + 255) / 256, 256>>>(f2w, pwf2, Cn, FFn);

    auto run_layer = [&](const float* xin_f32, const __half* xin_f16,
                         const float* qw, const float* qb,
                         const float* kw, const float* kb,
                         const float* vw, const float* vb,
                         const float* pw, const float* pb,
                         const float* lng, const float* lnb,
                         float* rout, __half* rout16) {
        qkv_pack_w16<<<(3 * Cn * Cn + 255) / 256, 256>>>(qw, kw, vw, pwqkv);
        qkv_pack_b<<<(3 * Cn + 255) / 256, 256>>>(qb, kb, vb, pbqkv);
        wt_pack16<<<(Cn * Cn + 255) / 256, 256>>>(pw, pwp, Cn, Cn);
        gemm_f16<<<dim3(3 * Cn / 128, BTn / 128), 256>>>(
            xin_f16, pwqkv, pbqkv, nullptr, nullptr, BTn, 3 * Cn, Cn, 2, pq16, pk16, pv16t);
        attn_mma<<<dim3(Tn / 64, Bn * Hn), 128>>>(pq16, pk16, pv16t, po16);
        gemm_f16<<<dim3(Cn / 128, BTn / 128), 256>>>(
            po16, pwp, pb, pp, nullptr, BTn, Cn, Cn, 0, nullptr, nullptr, nullptr);
        ln_res_k<<<BTn, 128>>>(xin_f32, pp, lng, lnb, rout, rout16);
    };

    run_layer(x,   px16, q1w, q1b, k1w, k1b, v1w, v1b, p1w, p1b, ln1g, ln1b, pr1, pr16);
    run_layer(pr1, pr16, q2w, q2b, k2w, k2b, v2w, v2b, p2w, p2b, ln2g, ln2b, pr2, pr16);

    gemm_f16<<<dim3(FFn / 128, BTn / 128), 256>>>(
        pr16, pwf1, f1b, nullptr, ph16, BTn, FFn, Cn, 1, nullptr, nullptr, nullptr);
    gemm_f16<<<dim3(Cn / 128, BTn / 128), 256>>>(
        ph16, pwf2, f2b, pp, nullptr, BTn, Cn, FFn, 0, nullptr, nullptr, nullptr);
    ln_res_k<<<BTn, 128>>>(pr2, pp, ln3g, ln3b, out, nullptr);
}

// round 9
// speedup vs baseline: 2.0601x; 1.0818x over previous
#include <cuda_runtime.h>
#include <cuda_fp16.h>
#include <math.h>

#define Bn 64
#define Tn 512
#define Cn 384
#define Hn 6
#define HDn 64
#define FFn 1536
#define BTn (Bn*Tn)
#define EPSn 1e-5f

#define SWS 20    // gemm smem row stride (u32 words)

// fp16 attention smem (u32 word strides)
#define STKW 36
#define STVW 20
#define BKS0 0
#define BVS0 (32*STKW)
#define BKS1 (BVS0 + 64*STVW)
#define BVS1 (BKS1 + 32*STKW)
#define BTOT (BVS1 + 64*STVW)

// ---------------- scratch ----------------
__device__ __half g_wqkv1[3*Cn*Cn];
__device__ __half g_wqkv2[3*Cn*Cn];
__device__ __half g_wp1[Cn*Cn];
__device__ __half g_wp2[Cn*Cn];
__device__ __half g_wf1t[FFn*Cn];
__device__ __half g_wf2t[Cn*FFn];
__device__ float  g_bqkv1[3*Cn];
__device__ float  g_bqkv2[3*Cn];
__device__ __half g_x16[(size_t)BTn*Cn];
__device__ __half g_o16[(size_t)BTn*Cn];
__device__ __half g_r16[(size_t)BTn*Cn];
__device__ __half g_h16[(size_t)BTn*FFn];
__device__ __half g_q16[(size_t)Bn*Hn*Tn*HDn];
__device__ __half g_k16[(size_t)Bn*Hn*Tn*HDn];
__device__ __half g_v16t[(size_t)Bn*Hn*HDn*Tn];
__device__ float g_p[(size_t)BTn*Cn];
__device__ float g_r1[(size_t)BTn*Cn];
__device__ float g_r2[(size_t)BTn*Cn];

// ---------------- fused prep: x->fp16, all weight/bias packs ----------------
#define SEG0 (BTn*Cn)            // x f2h
#define SEG1 (3*Cn*Cn)           // qkv w L1
#define SEG2 (3*Cn*Cn)           // qkv w L2
#define SEG3 (Cn*Cn)             // proj w L1
#define SEG4 (Cn*Cn)             // proj w L2
#define SEG5 (FFn*Cn)            // f1 w
#define SEG6 (Cn*FFn)            // f2 w
#define SEG7 (3*Cn)              // qkv b L1
#define SEG8 (3*Cn)              // qkv b L2
#define PTOT (SEG0+SEG1+SEG2+SEG3+SEG4+SEG5+SEG6+SEG7+SEG8)

__device__ __forceinline__ void pack_qkv_w(const float* qw, const float* kw,
                                           const float* vw, __half* o, int i) {
    int n = i / Cn, k = i % Cn;
    int mat = n / Cn, local = n % Cn;
    int h = local >> 6, d = local & 63;
    const float* w = (mat == 0) ? qw : (mat == 1) ? kw : vw;
    o[i] = __float2half(w[((size_t)h * Cn + k) * HDn + d]);
}
__device__ __forceinline__ void pack_wt(const float* w, __half* o, int N, int K, int i) {
    int n = i / K, k = i % K;
    o[i] = __float2half(w[(size_t)k * N + n]);
}

__global__ void prep_all(
    const float* __restrict__ x, __half* __restrict__ x16,
    const float* __restrict__ q1w, const float* __restrict__ k1w, const float* __restrict__ v1w,
    __half* __restrict__ wqkv1,
    const float* __restrict__ q2w, const float* __restrict__ k2w, const float* __restrict__ v2w,
    __half* __restrict__ wqkv2,
    const float* __restrict__ p1w, __half* __restrict__ wp1,
    const float* __restrict__ p2w, __half* __restrict__ wp2,
    const float* __restrict__ f1w, __half* __restrict__ wf1,
    const float* __restrict__ f2w, __half* __restrict__ wf2,
    const float* __restrict__ q1b, const float* __restrict__ k1b, const float* __restrict__ v1b,
    float* __restrict__ bqkv1,
    const float* __restrict__ q2b, const float* __restrict__ k2b, const float* __restrict__ v2b,
    float* __restrict__ bqkv2)
{
    int i = blockIdx.x * blockDim.x + threadIdx.x;
    if (i >= PTOT) return;
    if (i < SEG0) { x16[i] = __float2half(x[i]); return; }
    i -= SEG0;
    if (i < SEG1) { pack_qkv_w(q1w, k1w, v1w, wqkv1, i); return; }
    i -= SEG1;
    if (i < SEG2) { pack_qkv_w(q2w, k2w, v2w, wqkv2, i); return; }
    i -= SEG2;
    if (i < SEG3) { pack_wt(p1w, wp1, Cn, Cn, i); return; }
    i -= SEG3;
    if (i < SEG4) { pack_wt(p2w, wp2, Cn, Cn, i); return; }
    i -= SEG4;
    if (i < SEG5) { pack_wt(f1w, wf1, FFn, Cn, i); return; }
    i -= SEG5;
    if (i < SEG6) { pack_wt(f2w, wf2, Cn, FFn, i); return; }
    i -= SEG6;
    if (i < SEG7) {
        const float* b = (i < Cn) ? q1b : (i < 2 * Cn) ? k1b : v1b;
        bqkv1[i] = b[i % Cn]; return;
    }
    i -= SEG7;
    {
        const float* b = (i < Cn) ? q2b : (i < 2 * Cn) ? k2b : v2b;
        bqkv2[i] = b[i % Cn];
    }
}

// ---------------- mma / ldmatrix / async helpers ----------------
__device__ __forceinline__ void mma16(float* d, const unsigned* a, const unsigned* b) {
    asm("mma.sync.aligned.m16n8k16.row.col.f32.f16.f16.f32 "
        "{%0,%1,%2,%3},{%4,%5,%6,%7},{%8,%9},{%0,%1,%2,%3};"
        : "+f"(d[0]), "+f"(d[1]), "+f"(d[2]), "+f"(d[3])
        : "r"(a[0]), "r"(a[1]), "r"(a[2]), "r"(a[3]), "r"(b[0]), "r"(b[1]));
}
__device__ __forceinline__ void ldsm4(unsigned* r, unsigned addr) {
    asm volatile("ldmatrix.sync.aligned.m8n8.x4.shared.b16 {%0,%1,%2,%3}, [%4];"
        : "=r"(r[0]), "=r"(r[1]), "=r"(r[2]), "=r"(r[3]) : "r"(addr));
}
__device__ __forceinline__ void ldsm2(unsigned* r, unsigned addr) {
    asm volatile("ldmatrix.sync.aligned.m8n8.x2.shared.b16 {%0,%1}, [%2];"
        : "=r"(r[0]), "=r"(r[1]) : "r"(addr));
}
__device__ __forceinline__ unsigned h2u(float a, float b) {
    __half2 h = __floats2half2_rn(a, b);
    return *(unsigned*)&h;
}
__device__ __forceinline__ void cp_async16(void* smem_dst, const void* gsrc) {
    unsigned saddr = (unsigned)__cvta_generic_to_shared(smem_dst);
    asm volatile("cp.async.ca.shared.global [%0], [%1], 16;\n" :: "r"(saddr), "l"(gsrc));
}
#define CP_COMMIT() asm volatile("cp.async.commit_group;\n" ::: "memory")
#define CP_WAIT1()  asm volatile("cp.async.wait_group 1;\n" ::: "memory")
#define CP_WAIT0()  asm volatile("cp.async.wait_group 0;\n" ::: "memory")

// ---------------- fp16 GEMM with ldmatrix fragment loads --------------------------
// flags: 0 = fp32 out; 1 = relu + fp16 out; 2 = qkv scatter fp16 (+rope, q scaled)
__global__ __launch_bounds__(256) void gemm_f16(
    const __half* __restrict__ A, const __half* __restrict__ Bm,
    const float* __restrict__ bias, float* __restrict__ Cout,
    __half* __restrict__ Cout16,
    int M, int N, int K, int flags,
    __half* __restrict__ oq, __half* __restrict__ ok, __half* __restrict__ ov)
{
    __shared__ __align__(16) unsigned As[3][128 * SWS];
    __shared__ __align__(16) unsigned Bs[3][128 * SWS];

    const int tid = threadIdx.x;
    const int lane = tid & 31, warp = tid >> 5;
    const int warpM = warp >> 2, warpN = warp & 3;
    const int bm = blockIdx.y * 128, bn = blockIdx.x * 128;
    const int qq = lane & 3, gg = lane >> 2;

    const int sRow = tid >> 1;
    const int sOff = (tid & 1) * 8;
    const __half* Ap = A + (size_t)(bm + sRow) * K + (tid & 1) * 16;
    const __half* Bp = Bm + (size_t)(bn + sRow) * K + (tid & 1) * 16;

    // ldmatrix lane selectors
    const int arS = warpM * 64 + (lane & 7) + ((lane >> 3) & 1) * 8;
    const int acS = (lane >> 4) * 4;
    const int brS = warpN * 32 + (lane & 7);
    const int bcS = ((lane >> 3) & 1) * 4;

    unsigned aBase[3], bBase[3];
#pragma unroll
    for (int s = 0; s < 3; s++) {
        aBase[s] = (unsigned)__cvta_generic_to_shared(As[s]);
        bBase[s] = (unsigned)__cvta_generic_to_shared(Bs[s]);
    }

    float acc[4][4][4];
#pragma unroll
    for (int i = 0; i < 4; i++)
#pragma unroll
        for (int j = 0; j < 4; j++)
#pragma unroll
            for (int r = 0; r < 4; r++) acc[i][j][r] = 0.f;

    const int KT = K >> 5;

    {
        unsigned* as = As[0]; unsigned* bs = Bs[0];
        cp_async16(as + sRow * SWS + sOff,     Ap);
        cp_async16(as + sRow * SWS + sOff + 4, Ap + 8);
        cp_async16(bs + sRow * SWS + sOff,     Bp);
        cp_async16(bs + sRow * SWS + sOff + 4, Bp + 8);
    }
    CP_COMMIT();
    {
        unsigned* as = As[1]; unsigned* bs = Bs[1];
        cp_async16(as + sRow * SWS + sOff,     Ap + 32);
        cp_async16(as + sRow * SWS + sOff + 4, Ap + 40);
        cp_async16(bs + sRow * SWS + sOff,     Bp + 32);
        cp_async16(bs + sRow * SWS + sOff + 4, Bp + 40);
    }
    CP_COMMIT();

    for (int kt = 0; kt < KT; kt++) {
        CP_WAIT1();
        __syncthreads();

        if (kt + 2 < KT) {
            int st = (kt + 2) % 3;
            unsigned* as = As[st]; unsigned* bs = Bs[st];
            const __half* ap = Ap + (size_t)(kt + 2) * 32;
            const __half* bp = Bp + (size_t)(kt + 2) * 32;
            cp_async16(as + sRow * SWS + sOff,     ap);
            cp_async16(as + sRow * SWS + sOff + 4, ap + 8);
            cp_async16(bs + sRow * SWS + sOff,     bp);
            cp_async16(bs + sRow * SWS + sOff + 4, bp + 8);
        }
        CP_COMMIT();

        const unsigned ab = aBase[kt % 3];
        const unsigned bb = bBase[kt % 3];
#pragma unroll
        for (int ko = 0; ko < 16; ko += 8) {
            unsigned af[4][4], bf[4][2];
#pragma unroll
            for (int mi = 0; mi < 4; mi++)
                ldsm4(af[mi], ab + (((mi * 16 + arS) * SWS + ko + acS) << 2));
#pragma unroll
            for (int ni = 0; ni < 4; ni++)
                ldsm2(bf[ni], bb + (((ni * 8 + brS) * SWS + ko + bcS) << 2));
#pragma unroll
            for (int mi = 0; mi < 4; mi++)
#pragma unroll
                for (int ni = 0; ni < 4; ni++)
                    mma16(acc[mi][ni], af[mi], bf[ni]);
        }
    }

    const float scale = 0.051031036307982884f;   // 1/sqrt(384)
#pragma unroll
    for (int mi = 0; mi < 4; mi++) {
        int row0 = bm + warpM * 64 + mi * 16 + gg;
        float sn[2], cs[2];
        if (flags == 2) {
            sincosf((float)(row0 & 511), &sn[0], &cs[0]);
            sincosf((float)((row0 + 8) & 511), &sn[1], &cs[1]);
        }
#pragma unroll
        for (int ni = 0; ni < 4; ni++) {
            int col = bn + warpN * 32 + ni * 8 + qq * 2;
            float b0 = bias[col], b1 = bias[col + 1];
#pragma unroll
            for (int half = 0; half < 2; half++) {
                int row = row0 + half * 8;
                float xr = acc[mi][ni][half * 2 + 0] + b0;
                float xi = acc[mi][ni][half * 2 + 1] + b1;
                if (flags == 2) {
                    int mat = col / Cn;
                    if (mat < 2) {
                        float nr = cs[half] * xr - sn[half] * xi;
                        float ni2 = sn[half] * xr + cs[half] * xi;
                        xr = nr; xi = ni2;
                    }
                    int local = col - mat * Cn;
                    int h = local >> 6, d = local & 63;
                    int bbv = row >> 9, t = row & 511;
                    if (mat == 0) {
                        __half2 hv = __floats2half2_rn(xr * scale, xi * scale);
                        *(__half2*)(oq + ((size_t)(bbv * Hn + h) * Tn + t) * HDn + d) = hv;
                    } else if (mat == 1) {
                        __half2 hv = __floats2half2_rn(xr, xi);
                        *(__half2*)(ok + ((size_t)(bbv * Hn + h) * Tn + t) * HDn + d) = hv;
                    } else {
                        size_t vb = ((size_t)(bbv * Hn + h) * HDn + d) * Tn + t;
                        ov[vb]      = __float2half(xr);
                        ov[vb + Tn] = __float2half(xi);
                    }
                } else if (flags == 1) {
                    xr = fmaxf(xr, 0.f); xi = fmaxf(xi, 0.f);
                    __half2* p = (__half2*)(Cout16 + (size_t)row * N + col);
                    *p = __floats2half2_rn(xr, xi);
                } else {
                    float2* p = (float2*)(Cout + (size_t)row * N + col);
                    *p = make_float2(xr, xi);
                }
            }
        }
    }
}

// ---------------- fp16 tensor-core causal flash attention (ldmatrix K/V) ----------
__global__ __launch_bounds__(128) void attn_mma(
    const __half* __restrict__ q, const __half* __restrict__ k,
    const __half* __restrict__ v, __half* __restrict__ o)
{
    __shared__ __align__(16) unsigned sm[BTOT];

    const int bh = blockIdx.y;
    const int qt = gridDim.x - 1 - blockIdx.x;
    const int tid = threadIdx.x;
    const int warp = tid >> 5, lane = tid & 31;
    const int gg = lane >> 2, qq = lane & 3;
    const size_t base = (size_t)bh * Tn * HDn;
    const int q0 = qt * 64;
    const int ktiles = 2 * qt + 2;

    const int lrS = lane & 7;                 // ldmatrix row
    const int lcS = ((lane >> 3) & 1) * 4;    // ldmatrix col word

    {
        unsigned* kd = sm + BKS0;
        unsigned* vd = sm + BVS0;
#pragma unroll
        for (int i = 0; i < 2; i++) {
            int idx = i * 128 + tid;
            int r = idx >> 3, seg = idx & 7;
            cp_async16(kd + r * STKW + seg * 4, k + base + (size_t)r * 64 + seg * 8);
            int rv = idx >> 2, sv = idx & 3;
            cp_async16(vd + rv * STVW + sv * 4, v + base + (size_t)rv * Tn + sv * 8);
        }
        CP_COMMIT();
    }

    unsigned qf[4][4];
    {
        const __half* q0p = q + base + (size_t)(q0 + warp * 16 + gg) * 64;
        const __half* q1p = q0p + 8 * 64;
#pragma unroll
        for (int ks = 0; ks < 4; ks++) {
            qf[ks][0] = *(const unsigned*)(q0p + ks * 16 + 2 * qq);
            qf[ks][1] = *(const unsigned*)(q1p + ks * 16 + 2 * qq);
            qf[ks][2] = *(const unsigned*)(q0p + ks * 16 + 2 * qq + 8);
            qf[ks][3] = *(const unsigned*)(q1p + ks * 16 + 2 * qq + 8);
        }
    }
    CP_WAIT0();
    __syncthreads();

    float oacc[8][4];
#pragma unroll
    for (int i = 0; i < 8; i++)
#pragma unroll
        for (int r = 0; r < 4; r++) oacc[i][r] = 0.f;
    float m0 = -INFINITY, m1 = -INFINITY, l0 = 0.f, l1 = 0.f;

    const int row0g = q0 + warp * 16 + gg;
    const int row1g = row0g + 8;

    for (int kt = 0; kt < ktiles; kt++) {
        const int kbase = kt * 32;
        const unsigned ksBase = (unsigned)__cvta_generic_to_shared(sm + ((kt & 1) ? BKS1 : BKS0));
        const unsigned vsBase = (unsigned)__cvta_generic_to_shared(sm + ((kt & 1) ? BVS1 : BVS0));

        if (kt + 1 < ktiles) {
            unsigned* kd = sm + (((kt + 1) & 1) ? BKS1 : BKS0);
            unsigned* vd = sm + (((kt + 1) & 1) ? BVS1 : BVS0);
#pragma unroll
            for (int i = 0; i < 2; i++) {
                int idx = i * 128 + tid;
                int r = idx >> 3, seg = idx & 7;
                cp_async16(kd + r * STKW + seg * 4,
                           k + base + (size_t)(kbase + 32 + r) * 64 + seg * 8);
                int rv = idx >> 2, sv = idx & 3;
                cp_async16(vd + rv * STVW + sv * 4,
                           v + base + (size_t)rv * Tn + kbase + 32 + sv * 8);
            }
            CP_COMMIT();
        }

        // S = Q K^T
        float s[4][4];
#pragma unroll
        for (int nt = 0; nt < 4; nt++)
#pragma unroll
            for (int r = 0; r < 4; r++) s[nt][r] = 0.f;
#pragma unroll
        for (int ks = 0; ks < 4; ks++) {
            unsigned bf[4][2];
#pragma unroll
            for (int nt = 0; nt < 4; nt++)
                ldsm2(bf[nt], ksBase + (((nt * 8 + lrS) * STKW + ks * 8 + lcS) << 2));
#pragma unroll
            for (int nt = 0; nt < 4; nt++) mma16(s[nt], qf[ks], bf[nt]);
        }

        if (kt >= 2 * qt) {
#pragma unroll
            for (int nt = 0; nt < 4; nt++) {
                int c0 = kbase + nt * 8 + 2 * qq;
                if (c0 > row0g)     s[nt][0] = -1e30f;
                if (c0 + 1 > row0g) s[nt][1] = -1e30f;
                if (c0 > row1g)     s[nt][2] = -1e30f;
                if (c0 + 1 > row1g) s[nt][3] = -1e30f;
            }
        }

        float rm0 = -1e30f, rm1 = -1e30f;
#pragma unroll
        for (int nt = 0; nt < 4; nt++) {
            rm0 = fmaxf(rm0, fmaxf(s[nt][0], s[nt][1]));
            rm1 = fmaxf(rm1, fmaxf(s[nt][2], s[nt][3]));
        }
        rm0 = fmaxf(rm0, __shfl_xor_sync(0xffffffffu, rm0, 1));
        rm0 = fmaxf(rm0, __shfl_xor_sync(0xffffffffu, rm0, 2));
        rm1 = fmaxf(rm1, __shfl_xor_sync(0xffffffffu, rm1, 1));
        rm1 = fmaxf(rm1, __shfl_xor_sync(0xffffffffu, rm1, 2));
        float nm0 = fmaxf(m0, rm0), nm1 = fmaxf(m1, rm1);
        float corr0 = __expf(m0 - nm0), corr1 = __expf(m1 - nm1);
        float rs0 = 0.f, rs1 = 0.f;
#pragma unroll
        for (int nt = 0; nt < 4; nt++) {
            s[nt][0] = __expf(s[nt][0] - nm0);
            s[nt][1] = __expf(s[nt][1] - nm0);
            s[nt][2] = __expf(s[nt][2] - nm1);
            s[nt][3] = __expf(s[nt][3] - nm1);
            rs0 += s[nt][0] + s[nt][1];
            rs1 += s[nt][2] + s[nt][3];
        }
        rs0 += __shfl_xor_sync(0xffffffffu, rs0, 1);
        rs0 += __shfl_xor_sync(0xffffffffu, rs0, 2);
        rs1 += __shfl_xor_sync(0xffffffffu, rs1, 1);
        rs1 += __shfl_xor_sync(0xffffffffu, rs1, 2);
        l0 = l0 * corr0 + rs0;
        l1 = l1 * corr1 + rs1;
        m0 = nm0; m1 = nm1;
#pragma unroll
        for (int nt = 0; nt < 8; nt++) {
            oacc[nt][0] *= corr0; oacc[nt][1] *= corr0;
            oacc[nt][2] *= corr1; oacc[nt][3] *= corr1;
        }

        unsigned pa[2][4];
        pa[0][0] = h2u(s[0][0], s[0][1]);
        pa[0][1] = h2u(s[0][2], s[0][3]);
        pa[0][2] = h2u(s[1][0], s[1][1]);
        pa[0][3] = h2u(s[1][2], s[1][3]);
        pa[1][0] = h2u(s[2][0], s[2][1]);
        pa[1][1] = h2u(s[2][2], s[2][3]);
        pa[1][2] = h2u(s[3][0], s[3][1]);
        pa[1][3] = h2u(s[3][2], s[3][3]);

#pragma unroll
        for (int ks = 0; ks < 2; ks++) {
#pragma unroll
            for (int nt = 0; nt < 8; nt++) {
                unsigned bf2[2];
                ldsm2(bf2, vsBase + (((nt * 8 + lrS) * STVW + ks * 8 + lcS) << 2));
                mma16(oacc[nt], pa[ks], bf2);
            }
        }

        if (kt + 1 < ktiles) {
            CP_WAIT0();
            __syncthreads();
        }
    }

    const float inv0 = 1.f / l0, inv1 = 1.f / l1;
    const int b = bh / Hn, h = bh % Hn;
    __half* p0 = o + ((size_t)(b * Tn + row0g)) * Cn + h * 64;
    __half* p1 = o + ((size_t)(b * Tn + row1g)) * Cn + h * 64;
#pragma unroll
    for (int nt = 0; nt < 8; nt++) {
        *(__half2*)(p0 + nt * 8 + 2 * qq) = __floats2half2_rn(oacc[nt][0] * inv0, oacc[nt][1] * inv0);
        *(__half2*)(p1 + nt * 8 + 2 * qq) = __floats2half2_rn(oacc[nt][2] * inv1, oacc[nt][3] * inv1);
    }
}

// ---------------- fused residual + LayerNorm: 2 rows per 256-thread block ---------
__global__ __launch_bounds__(256) void ln_res_k(
    const float* __restrict__ x, const float* __restrict__ y,
    const float* __restrict__ g, const float* __restrict__ bb,
    float* __restrict__ out, __half* __restrict__ out16)
{
    __shared__ float red[8];
    const int half = threadIdx.x >> 7;            // 0 or 1
    const int tid = threadIdx.x & 127;
    const int row = blockIdx.x * 2 + half;
    const size_t base = (size_t)row * Cn;
    float v0 = x[base + tid]       + y[base + tid];
    float v1 = x[base + tid + 128] + y[base + tid + 128];
    float v2 = x[base + tid + 256] + y[base + tid + 256];

    float s = v0 + v1 + v2;
    for (int o = 16; o > 0; o >>= 1) s += __shfl_xor_sync(0xffffffffu, s, o);
    if ((tid & 31) == 0) red[half * 4 + (tid >> 5)] = s;
    __syncthreads();
    float mean = (red[half * 4] + red[half * 4 + 1] + red[half * 4 + 2] + red[half * 4 + 3]) * (1.f / Cn);
    __syncthreads();

    float d0 = v0 - mean, d1 = v1 - mean, d2 = v2 - mean;
    float sq = d0 * d0 + d1 * d1 + d2 * d2;
    for (int o = 16; o > 0; o >>= 1) sq += __shfl_xor_sync(0xffffffffu, sq, o);
    if ((tid & 31) == 0) red[half * 4 + (tid >> 5)] = sq;
    __syncthreads();
    float var = (red[half * 4] + red[half * 4 + 1] + red[half * 4 + 2] + red[half * 4 + 3]) * (1.f / Cn);
    float inv = rsqrtf(var + EPSn);

    float o0 = g[tid]       * d0 * inv + bb[tid];
    float o1 = g[tid + 128] * d1 * inv + bb[tid + 128];
    float o2 = g[tid + 256] * d2 * inv + bb[tid + 256];
    out[base + tid]       = o0;
    out[base + tid + 128] = o1;
    out[base + tid + 256] = o2;
    if (out16) {
        out16[base + tid]       = __float2half(o0);
        out16[base + tid + 128] = __float2half(o1);
        out16[base + tid + 256] = __float2half(o2);
    }
}

// ---------------- host orchestration ----------------
extern "C" void kernel_launch(void* const* d_in, const int* in_sizes, int n_in,
                              void* d_out, int out_size)
{
    (void)in_sizes; (void)n_in; (void)out_size;
    const float* x    = (const float*)d_in[0];
    const float* q1w  = (const float*)d_in[1];
    const float* q1b  = (const float*)d_in[2];
    const float* k1w  = (const float*)d_in[3];
    const float* k1b  = (const float*)d_in[4];
    const float* v1w  = (const float*)d_in[5];
    const float* v1b  = (const float*)d_in[6];
    const float* p1w  = (const float*)d_in[7];
    const float* p1b  = (const float*)d_in[8];
    const float* ln1g = (const float*)d_in[9];
    const float* ln1b = (const float*)d_in[10];
    const float* q2w  = (const float*)d_in[11];
    const float* q2b  = (const float*)d_in[12];
    const float* k2w  = (const float*)d_in[13];
    const float* k2b  = (const float*)d_in[14];
    const float* v2w  = (const float*)d_in[15];
    const float* v2b  = (const float*)d_in[16];
    const float* p2w  = (const float*)d_in[17];
    const float* p2b  = (const float*)d_in[18];
    const float* ln2g = (const float*)d_in[19];
    const float* ln2b = (const float*)d_in[20];
    const float* f1w  = (const float*)d_in[21];
    const float* f1b  = (const float*)d_in[22];
    const float* f2w  = (const float*)d_in[23];
    const float* f2b  = (const float*)d_in[24];
    const float* ln3g = (const float*)d_in[25];
    const float* ln3b = (const float*)d_in[26];
    float* out = (float*)d_out;

    __half *pwqkv1, *pwqkv2, *pwp1, *pwp2, *pwf1, *pwf2;
    __half *px16, *po16, *pr16, *ph16, *pq16, *pk16, *pv16t;
    float *pbqkv1, *pbqkv2, *pp, *pr1, *pr2;
    cudaGetSymbolAddress((void**)&pwqkv1, g_wqkv1);
    cudaGetSymbolAddress((void**)&pwqkv2, g_wqkv2);
    cudaGetSymbolAddress((void**)&pwp1, g_wp1);
    cudaGetSymbolAddress((void**)&pwp2, g_wp2);
    cudaGetSymbolAddress((void**)&pwf1, g_wf1t);
    cudaGetSymbolAddress((void**)&pwf2, g_wf2t);
    cudaGetSymbolAddress((void**)&px16, g_x16);
    cudaGetSymbolAddress((void**)&po16, g_o16);
    cudaGetSymbolAddress((void**)&pr16, g_r16);
    cudaGetSymbolAddress((void**)&ph16, g_h16);
    cudaGetSymbolAddress((void**)&pq16, g_q16);
    cudaGetSymbolAddress((void**)&pk16, g_k16);
    cudaGetSymbolAddress((void**)&pv16t, g_v16t);
    cudaGetSymbolAddress((void**)&pbqkv1, g_bqkv1);
    cudaGetSymbolAddress((void**)&pbqkv2, g_bqkv2);
    cudaGetSymbolAddress((void**)&pp,  g_p);
    cudaGetSymbolAddress((void**)&pr1, g_r1);
    cudaGetSymbolAddress((void**)&pr2, g_r2);

    prep_all<<<(PTOT + 255) / 256, 256>>>(
        x, px16,
        q1w, k1w, v1w, pwqkv1,
        q2w, k2w, v2w, pwqkv2,
        p1w, pwp1, p2w, pwp2,
        f1w, pwf1, f2w, pwf2,
        q1b, k1b, v1b, pbqkv1,
        q2b, k2b, v2b, pbqkv2);

    auto run_layer = [&](const float* xin_f32, const __half* xin_f16,
                         const __half* wqkv, const float* bqkv, const __half* wp,
                         const float* pb, const float* lng, const float* lnb,
                         float* rout, __half* rout16) {
        gemm_f16<<<dim3(3 * Cn / 128, BTn / 128), 256>>>(
            xin_f16, wqkv, bqkv, nullptr, nullptr, BTn, 3 * Cn, Cn, 2, pq16, pk16, pv16t);
        attn_mma<<<dim3(Tn / 64, Bn * Hn), 128>>>(pq16, pk16, pv16t, po16);
        gemm_f16<<<dim3(Cn / 128, BTn / 128), 256>>>(
            po16, wp, pb, pp, nullptr, BTn, Cn, Cn, 0, nullptr, nullptr, nullptr);
        ln_res_k<<<BTn / 2, 256>>>(xin_f32, pp, lng, lnb, rout, rout16);
    };

    run_layer(x,   px16, pwqkv1, pbqkv1, pwp1, p1b, ln1g, ln1b, pr1, pr16);
    run_layer(pr1, pr16, pwqkv2, pbqkv2, pwp2, p2b, ln2g, ln2b, pr2, pr16);

    gemm_f16<<<dim3(FFn / 128, BTn / 128), 256>>>(
        pr16, pwf1, f1b, nullptr, ph16, BTn, FFn, Cn, 1, nullptr, nullptr, nullptr);
    gemm_f16<<<dim3(Cn / 128, BTn / 128), 256>>>(
        ph16, pwf2, f2b, pp, nullptr, BTn, Cn, FFn, 0, nullptr, nullptr, nullptr);
    ln_res_k<<<BTn / 2, 256>>>(pr2, pp, ln3g, ln3b, out, nullptr);
}

// round 10
// speedup vs baseline: 2.0950x; 1.0169x over previous
#include <cuda_runtime.h>
#include <cuda_fp16.h>
#include <math.h>

#define Bn 64
#define Tn 512
#define Cn 384
#define Hn 6
#define HDn 64
#define FFn 1536
#define BTn (Bn*Tn)
#define EPSn 1e-5f

#define SWS 20    // gemm smem row stride (u32 words)

// fp16 attention smem (u32 word strides)
#define STKW 36
#define STVW 20
#define BKS0 0
#define BVS0 (32*STKW)
#define BKS1 (BVS0 + 64*STVW)
#define BVS1 (BKS1 + 32*STKW)
#define BTOT (BVS1 + 64*STVW)

// ---------------- scratch ----------------
__device__ __half g_wqkv1[3*Cn*Cn];
__device__ __half g_wqkv2[3*Cn*Cn];
__device__ __half g_wp1[Cn*Cn];
__device__ __half g_wp2[Cn*Cn];
__device__ __half g_wf1t[FFn*Cn];
__device__ __half g_wf2t[Cn*FFn];
__device__ float  g_bqkv1[3*Cn];
__device__ float  g_bqkv2[3*Cn];
__device__ __half g_x16[(size_t)BTn*Cn];
__device__ __half g_o16[(size_t)BTn*Cn];
__device__ __half g_r16[(size_t)BTn*Cn];
__device__ __half g_h16[(size_t)BTn*FFn];
__device__ __half g_q16[(size_t)Bn*Hn*Tn*HDn];
__device__ __half g_k16[(size_t)Bn*Hn*Tn*HDn];
__device__ __half g_v16t[(size_t)Bn*Hn*HDn*Tn];
__device__ float g_p[(size_t)BTn*Cn];
__device__ float g_r1[(size_t)BTn*Cn];
__device__ float g_r2[(size_t)BTn*Cn];

// ---------------- fused prep ----------------
#define SEG0 (BTn*Cn)
#define SEG1 (3*Cn*Cn)
#define SEG2 (3*Cn*Cn)
#define SEG3 (Cn*Cn)
#define SEG4 (Cn*Cn)
#define SEG5 (FFn*Cn)
#define SEG6 (Cn*FFn)
#define SEG7 (3*Cn)
#define SEG8 (3*Cn)
#define PTOT (SEG0+SEG1+SEG2+SEG3+SEG4+SEG5+SEG6+SEG7+SEG8)

__device__ __forceinline__ void pack_qkv_w(const float* qw, const float* kw,
                                           const float* vw, __half* o, int i) {
    int n = i / Cn, k = i % Cn;
    int mat = n / Cn, local = n % Cn;
    int h = local >> 6, d = local & 63;
    const float* w = (mat == 0) ? qw : (mat == 1) ? kw : vw;
    o[i] = __float2half(w[((size_t)h * Cn + k) * HDn + d]);
}
__device__ __forceinline__ void pack_wt(const float* w, __half* o, int N, int K, int i) {
    int n = i / K, k = i % K;
    o[i] = __float2half(w[(size_t)k * N + n]);
}

__global__ void prep_all(
    const float* __restrict__ x, __half* __restrict__ x16,
    const float* __restrict__ q1w, const float* __restrict__ k1w, const float* __restrict__ v1w,
    __half* __restrict__ wqkv1,
    const float* __restrict__ q2w, const float* __restrict__ k2w, const float* __restrict__ v2w,
    __half* __restrict__ wqkv2,
    const float* __restrict__ p1w, __half* __restrict__ wp1,
    const float* __restrict__ p2w, __half* __restrict__ wp2,
    const float* __restrict__ f1w, __half* __restrict__ wf1,
    const float* __restrict__ f2w, __half* __restrict__ wf2,
    const float* __restrict__ q1b, const float* __restrict__ k1b, const float* __restrict__ v1b,
    float* __restrict__ bqkv1,
    const float* __restrict__ q2b, const float* __restrict__ k2b, const float* __restrict__ v2b,
    float* __restrict__ bqkv2)
{
    int i = blockIdx.x * blockDim.x + threadIdx.x;
    if (i >= PTOT) return;
    if (i < SEG0) { x16[i] = __float2half(x[i]); return; }
    i -= SEG0;
    if (i < SEG1) { pack_qkv_w(q1w, k1w, v1w, wqkv1, i); return; }
    i -= SEG1;
    if (i < SEG2) { pack_qkv_w(q2w, k2w, v2w, wqkv2, i); return; }
    i -= SEG2;
    if (i < SEG3) { pack_wt(p1w, wp1, Cn, Cn, i); return; }
    i -= SEG3;
    if (i < SEG4) { pack_wt(p2w, wp2, Cn, Cn, i); return; }
    i -= SEG4;
    if (i < SEG5) { pack_wt(f1w, wf1, FFn, Cn, i); return; }
    i -= SEG5;
    if (i < SEG6) { pack_wt(f2w, wf2, Cn, FFn, i); return; }
    i -= SEG6;
    if (i < SEG7) {
        const float* b = (i < Cn) ? q1b : (i < 2 * Cn) ? k1b : v1b;
        bqkv1[i] = b[i % Cn]; return;
    }
    i -= SEG7;
    {
        const float* b = (i < Cn) ? q2b : (i < 2 * Cn) ? k2b : v2b;
        bqkv2[i] = b[i % Cn];
    }
}

// ---------------- mma / ldmatrix / async helpers ----------------
__device__ __forceinline__ void mma16(float* d, const unsigned* a, const unsigned* b) {
    asm("mma.sync.aligned.m16n8k16.row.col.f32.f16.f16.f32 "
        "{%0,%1,%2,%3},{%4,%5,%6,%7},{%8,%9},{%0,%1,%2,%3};"
        : "+f"(d[0]), "+f"(d[1]), "+f"(d[2]), "+f"(d[3])
        : "r"(a[0]), "r"(a[1]), "r"(a[2]), "r"(a[3]), "r"(b[0]), "r"(b[1]));
}
__device__ __forceinline__ void ldsm4(unsigned* r, unsigned addr) {
    asm volatile("ldmatrix.sync.aligned.m8n8.x4.shared.b16 {%0,%1,%2,%3}, [%4];"
        : "=r"(r[0]), "=r"(r[1]), "=r"(r[2]), "=r"(r[3]) : "r"(addr));
}
__device__ __forceinline__ void ldsm2(unsigned* r, unsigned addr) {
    asm volatile("ldmatrix.sync.aligned.m8n8.x2.shared.b16 {%0,%1}, [%2];"
        : "=r"(r[0]), "=r"(r[1]) : "r"(addr));
}
__device__ __forceinline__ unsigned h2u(float a, float b) {
    __half2 h = __floats2half2_rn(a, b);
    return *(unsigned*)&h;
}
__device__ __forceinline__ void cp_async16(void* smem_dst, const void* gsrc) {
    unsigned saddr = (unsigned)__cvta_generic_to_shared(smem_dst);
    asm volatile("cp.async.ca.shared.global [%0], [%1], 16;\n" :: "r"(saddr), "l"(gsrc));
}
#define CP_COMMIT() asm volatile("cp.async.commit_group;\n" ::: "memory")
#define CP_WAIT0()  asm volatile("cp.async.wait_group 0;\n" ::: "memory")

// ---------------- fp16 GEMM: 4-stage pipeline, one barrier per 2 k-iterations -----
// flags: 0 = fp32 out; 1 = relu + fp16 out; 2 = qkv scatter fp16 (+rope, q scaled)
__global__ __launch_bounds__(256) void gemm_f16(
    const __half* __restrict__ A, const __half* __restrict__ Bm,
    const float* __restrict__ bias, float* __restrict__ Cout,
    __half* __restrict__ Cout16,
    int M, int N, int K, int flags,
    __half* __restrict__ oq, __half* __restrict__ ok, __half* __restrict__ ov)
{
    __shared__ __align__(16) unsigned As[4][128 * SWS];
    __shared__ __align__(16) unsigned Bs[4][128 * SWS];

    const int tid = threadIdx.x;
    const int lane = tid & 31, warp = tid >> 5;
    const int warpM = warp >> 2, warpN = warp & 3;
    const int bm = blockIdx.y * 128, bn = blockIdx.x * 128;
    const int qq = lane & 3, gg = lane >> 2;

    const int sRow = tid >> 1;
    const int sOff = (tid & 1) * 8;
    const __half* Ap = A + (size_t)(bm + sRow) * K + (tid & 1) * 16;
    const __half* Bp = Bm + (size_t)(bn + sRow) * K + (tid & 1) * 16;

    const int arS = warpM * 64 + (lane & 7) + ((lane >> 3) & 1) * 8;
    const int acS = (lane >> 4) * 4;
    const int brS = warpN * 32 + (lane & 7);
    const int bcS = ((lane >> 3) & 1) * 4;

    unsigned aBase[4], bBase[4];
#pragma unroll
    for (int s = 0; s < 4; s++) {
        aBase[s] = (unsigned)__cvta_generic_to_shared(As[s]);
        bBase[s] = (unsigned)__cvta_generic_to_shared(Bs[s]);
    }

    float acc[4][4][4];
#pragma unroll
    for (int i = 0; i < 4; i++)
#pragma unroll
        for (int j = 0; j < 4; j++)
#pragma unroll
            for (int r = 0; r < 4; r++) acc[i][j][r] = 0.f;

    const int KT = K >> 5;   // always even here (12 or 48)

    // prologue: stages 0 and 1, one commit group
    {
        unsigned* as0 = As[0]; unsigned* bs0 = Bs[0];
        cp_async16(as0 + sRow * SWS + sOff,     Ap);
        cp_async16(as0 + sRow * SWS + sOff + 4, Ap + 8);
        cp_async16(bs0 + sRow * SWS + sOff,     Bp);
        cp_async16(bs0 + sRow * SWS + sOff + 4, Bp + 8);
        unsigned* as1 = As[1]; unsigned* bs1 = Bs[1];
        cp_async16(as1 + sRow * SWS + sOff,     Ap + 32);
        cp_async16(as1 + sRow * SWS + sOff + 4, Ap + 40);
        cp_async16(bs1 + sRow * SWS + sOff,     Bp + 32);
        cp_async16(bs1 + sRow * SWS + sOff + 4, Bp + 40);
    }
    CP_COMMIT();

    for (int kt2 = 0; kt2 < KT; kt2 += 2) {
        CP_WAIT0();
        __syncthreads();

        if (kt2 + 2 < KT) {
            int stA = (kt2 + 2) & 3, stB = (kt2 + 3) & 3;
            const __half* apA = Ap + (size_t)(kt2 + 2) * 32;
            const __half* bpA = Bp + (size_t)(kt2 + 2) * 32;
            unsigned* as = As[stA]; unsigned* bs = Bs[stA];
            cp_async16(as + sRow * SWS + sOff,     apA);
            cp_async16(as + sRow * SWS + sOff + 4, apA + 8);
            cp_async16(bs + sRow * SWS + sOff,     bpA);
            cp_async16(bs + sRow * SWS + sOff + 4, bpA + 8);
            unsigned* as2 = As[stB]; unsigned* bs2 = Bs[stB];
            cp_async16(as2 + sRow * SWS + sOff,     apA + 32);
            cp_async16(as2 + sRow * SWS + sOff + 4, apA + 40);
            cp_async16(bs2 + sRow * SWS + sOff,     bpA + 32);
            cp_async16(bs2 + sRow * SWS + sOff + 4, bpA + 40);
            CP_COMMIT();
        }

#pragma unroll
        for (int sub = 0; sub < 2; sub++) {
            const unsigned ab = aBase[(kt2 + sub) & 3];
            const unsigned bb = bBase[(kt2 + sub) & 3];
#pragma unroll
            for (int ko = 0; ko < 16; ko += 8) {
                unsigned af[4][4], bf[4][2];
#pragma unroll
                for (int mi = 0; mi < 4; mi++)
                    ldsm4(af[mi], ab + (((mi * 16 + arS) * SWS + ko + acS) << 2));
#pragma unroll
                for (int ni = 0; ni < 4; ni++)
                    ldsm2(bf[ni], bb + (((ni * 8 + brS) * SWS + ko + bcS) << 2));
#pragma unroll
                for (int mi = 0; mi < 4; mi++)
#pragma unroll
                    for (int ni = 0; ni < 4; ni++)
                        mma16(acc[mi][ni], af[mi], bf[ni]);
            }
        }
    }

    const float scale = 0.051031036307982884f;   // 1/sqrt(384)
#pragma unroll
    for (int mi = 0; mi < 4; mi++) {
        int row0 = bm + warpM * 64 + mi * 16 + gg;
        float sn[2], cs[2];
        if (flags == 2) {
            sincosf((float)(row0 & 511), &sn[0], &cs[0]);
            sincosf((float)((row0 + 8) & 511), &sn[1], &cs[1]);
        }
#pragma unroll
        for (int ni = 0; ni < 4; ni++) {
            int col = bn + warpN * 32 + ni * 8 + qq * 2;
            float b0 = bias[col], b1 = bias[col + 1];
#pragma unroll
            for (int half = 0; half < 2; half++) {
                int row = row0 + half * 8;
                float xr = acc[mi][ni][half * 2 + 0] + b0;
                float xi = acc[mi][ni][half * 2 + 1] + b1;
                if (flags == 2) {
                    int mat = col / Cn;
                    if (mat < 2) {
                        float nr = cs[half] * xr - sn[half] * xi;
                        float ni2 = sn[half] * xr + cs[half] * xi;
                        xr = nr; xi = ni2;
                    }
                    int local = col - mat * Cn;
                    int h = local >> 6, d = local & 63;
                    int bbv = row >> 9, t = row & 511;
                    if (mat == 0) {
                        __half2 hv = __floats2half2_rn(xr * scale, xi * scale);
                        *(__half2*)(oq + ((size_t)(bbv * Hn + h) * Tn + t) * HDn + d) = hv;
                    } else if (mat == 1) {
                        __half2 hv = __floats2half2_rn(xr, xi);
                        *(__half2*)(ok + ((size_t)(bbv * Hn + h) * Tn + t) * HDn + d) = hv;
                    } else {
                        size_t vb = ((size_t)(bbv * Hn + h) * HDn + d) * Tn + t;
                        ov[vb]      = __float2half(xr);
                        ov[vb + Tn] = __float2half(xi);
                    }
                } else if (flags == 1) {
                    xr = fmaxf(xr, 0.f); xi = fmaxf(xi, 0.f);
                    __half2* p = (__half2*)(Cout16 + (size_t)row * N + col);
                    *p = __floats2half2_rn(xr, xi);
                } else {
                    float2* p = (float2*)(Cout + (size_t)row * N + col);
                    *p = make_float2(xr, xi);
                }
            }
        }
    }
}

// ---------------- fp16 causal flash attention: 128-query tile, 256 threads --------
__global__ __launch_bounds__(256) void attn_mma(
    const __half* __restrict__ q, const __half* __restrict__ k,
    const __half* __restrict__ v, __half* __restrict__ o)
{
    __shared__ __align__(16) unsigned sm[BTOT];

    const int bh = blockIdx.y;
    const int qt = gridDim.x - 1 - blockIdx.x;   // long blocks first
    const int tid = threadIdx.x;
    const int warp = tid >> 5, lane = tid & 31;
    const int gg = lane >> 2, qq = lane & 3;
    const size_t base = (size_t)bh * Tn * HDn;
    const int q0 = qt * 128;
    const int ktiles = 4 * qt + 4;

    const int lrS = lane & 7;
    const int lcS = ((lane >> 3) & 1) * 4;

    // prefetch KV tile 0 (one cp.async16 per thread per tensor)
    {
        unsigned* kd = sm + BKS0;
        unsigned* vd = sm + BVS0;
        int r = tid >> 3, seg = tid & 7;
        cp_async16(kd + r * STKW + seg * 4, k + base + (size_t)r * 64 + seg * 8);
        int rv = tid >> 2, sv = tid & 3;
        cp_async16(vd + rv * STVW + sv * 4, v + base + (size_t)rv * Tn + sv * 8);
        CP_COMMIT();
    }

    unsigned qf[4][4];
    {
        const __half* q0p = q + base + (size_t)(q0 + warp * 16 + gg) * 64;
        const __half* q1p = q0p + 8 * 64;
#pragma unroll
        for (int ks = 0; ks < 4; ks++) {
            qf[ks][0] = *(const unsigned*)(q0p + ks * 16 + 2 * qq);
            qf[ks][1] = *(const unsigned*)(q1p + ks * 16 + 2 * qq);
            qf[ks][2] = *(const unsigned*)(q0p + ks * 16 + 2 * qq + 8);
            qf[ks][3] = *(const unsigned*)(q1p + ks * 16 + 2 * qq + 8);
        }
    }
    CP_WAIT0();
    __syncthreads();

    float oacc[8][4];
#pragma unroll
    for (int i = 0; i < 8; i++)
#pragma unroll
        for (int r = 0; r < 4; r++) oacc[i][r] = 0.f;
    float m0 = -INFINITY, m1 = -INFINITY, l0 = 0.f, l1 = 0.f;

    const int row0g = q0 + warp * 16 + gg;
    const int row1g = row0g + 8;

    for (int kt = 0; kt < ktiles; kt++) {
        const int kbase = kt * 32;
        const unsigned ksBase = (unsigned)__cvta_generic_to_shared(sm + ((kt & 1) ? BKS1 : BKS0));
        const unsigned vsBase = (unsigned)__cvta_generic_to_shared(sm + ((kt & 1) ? BVS1 : BVS0));

        if (kt + 1 < ktiles) {
            unsigned* kd = sm + (((kt + 1) & 1) ? BKS1 : BKS0);
            unsigned* vd = sm + (((kt + 1) & 1) ? BVS1 : BVS0);
            int r = tid >> 3, seg = tid & 7;
            cp_async16(kd + r * STKW + seg * 4,
                       k + base + (size_t)(kbase + 32 + r) * 64 + seg * 8);
            int rv = tid >> 2, sv = tid & 3;
            cp_async16(vd + rv * STVW + sv * 4,
                       v + base + (size_t)rv * Tn + kbase + 32 + sv * 8);
            CP_COMMIT();
        }

        // S = Q K^T
        float s[4][4];
#pragma unroll
        for (int nt = 0; nt < 4; nt++)
#pragma unroll
            for (int r = 0; r < 4; r++) s[nt][r] = 0.f;
#pragma unroll
        for (int ks = 0; ks < 4; ks++) {
            unsigned bf[4][2];
#pragma unroll
            for (int nt = 0; nt < 4; nt++)
                ldsm2(bf[nt], ksBase + (((nt * 8 + lrS) * STKW + ks * 8 + lcS) << 2));
#pragma unroll
            for (int nt = 0; nt < 4; nt++) mma16(s[nt], qf[ks], bf[nt]);
        }

        // causal mask (tiles overlapping/after the diagonal for this 128-row block)
        if (kt >= 4 * qt) {
#pragma unroll
            for (int nt = 0; nt < 4; nt++) {
                int c0 = kbase + nt * 8 + 2 * qq;
                if (c0 > row0g)     s[nt][0] = -1e30f;
                if (c0 + 1 > row0g) s[nt][1] = -1e30f;
                if (c0 > row1g)     s[nt][2] = -1e30f;
                if (c0 + 1 > row1g) s[nt][3] = -1e30f;
            }
        }

        float rm0 = -1e30f, rm1 = -1e30f;
#pragma unroll
        for (int nt = 0; nt < 4; nt++) {
            rm0 = fmaxf(rm0, fmaxf(s[nt][0], s[nt][1]));
            rm1 = fmaxf(rm1, fmaxf(s[nt][2], s[nt][3]));
        }
        rm0 = fmaxf(rm0, __shfl_xor_sync(0xffffffffu, rm0, 1));
        rm0 = fmaxf(rm0, __shfl_xor_sync(0xffffffffu, rm0, 2));
        rm1 = fmaxf(rm1, __shfl_xor_sync(0xffffffffu, rm1, 1));
        rm1 = fmaxf(rm1, __shfl_xor_sync(0xffffffffu, rm1, 2));
        float nm0 = fmaxf(m0, rm0), nm1 = fmaxf(m1, rm1);
        float corr0 = __expf(m0 - nm0), corr1 = __expf(m1 - nm1);
        float rs0 = 0.f, rs1 = 0.f;
#pragma unroll
        for (int nt = 0; nt < 4; nt++) {
            s[nt][0] = __expf(s[nt][0] - nm0);
            s[nt][1] = __expf(s[nt][1] - nm0);
            s[nt][2] = __expf(s[nt][2] - nm1);
            s[nt][3] = __expf(s[nt][3] - nm1);
            rs0 += s[nt][0] + s[nt][1];
            rs1 += s[nt][2] + s[nt][3];
        }
        rs0 += __shfl_xor_sync(0xffffffffu, rs0, 1);
        rs0 += __shfl_xor_sync(0xffffffffu, rs0, 2);
        rs1 += __shfl_xor_sync(0xffffffffu, rs1, 1);
        rs1 += __shfl_xor_sync(0xffffffffu, rs1, 2);
        l0 = l0 * corr0 + rs0;
        l1 = l1 * corr1 + rs1;
        m0 = nm0; m1 = nm1;
#pragma unroll
        for (int nt = 0; nt < 8; nt++) {
            oacc[nt][0] *= corr0; oacc[nt][1] *= corr0;
            oacc[nt][2] *= corr1; oacc[nt][3] *= corr1;
        }

        unsigned pa[2][4];
        pa[0][0] = h2u(s[0][0], s[0][1]);
        pa[0][1] = h2u(s[0][2], s[0][3]);
        pa[0][2] = h2u(s[1][0], s[1][1]);
        pa[0][3] = h2u(s[1][2], s[1][3]);
        pa[1][0] = h2u(s[2][0], s[2][1]);
        pa[1][1] = h2u(s[2][2], s[2][3]);
        pa[1][2] = h2u(s[3][0], s[3][1]);
        pa[1][3] = h2u(s[3][2], s[3][3]);

#pragma unroll
        for (int ks = 0; ks < 2; ks++) {
#pragma unroll
            for (int nt = 0; nt < 8; nt++) {
                unsigned bf2[2];
                ldsm2(bf2, vsBase + (((nt * 8 + lrS) * STVW + ks * 8 + lcS) << 2));
                mma16(oacc[nt], pa[ks], bf2);
            }
        }

        if (kt + 1 < ktiles) {
            CP_WAIT0();
            __syncthreads();
        }
    }

    const float inv0 = 1.f / l0, inv1 = 1.f / l1;
    const int b = bh / Hn, h = bh % Hn;
    __half* p0 = o + ((size_t)(b * Tn + row0g)) * Cn + h * 64;
    __half* p1 = o + ((size_t)(b * Tn + row1g)) * Cn + h * 64;
#pragma unroll
    for (int nt = 0; nt < 8; nt++) {
        *(__half2*)(p0 + nt * 8 + 2 * qq) = __floats2half2_rn(oacc[nt][0] * inv0, oacc[nt][1] * inv0);
        *(__half2*)(p1 + nt * 8 + 2 * qq) = __floats2half2_rn(oacc[nt][2] * inv1, oacc[nt][3] * inv1);
    }
}

// ---------------- fused residual + LayerNorm: 2 rows per 256-thread block ---------
__global__ __launch_bounds__(256) void ln_res_k(
    const float* __restrict__ x, const float* __restrict__ y,
    const float* __restrict__ g, const float* __restrict__ bb,
    float* __restrict__ out, __half* __restrict__ out16)
{
    __shared__ float red[8];
    const int half = threadIdx.x >> 7;
    const int tid = threadIdx.x & 127;
    const int row = blockIdx.x * 2 + half;
    const size_t base = (size_t)row * Cn;
    float v0 = x[base + tid]       + y[base + tid];
    float v1 = x[base + tid + 128] + y[base + tid + 128];
    float v2 = x[base + tid + 256] + y[base + tid + 256];

    float s = v0 + v1 + v2;
    for (int o = 16; o > 0; o >>= 1) s += __shfl_xor_sync(0xffffffffu, s, o);
    if ((tid & 31) == 0) red[half * 4 + (tid >> 5)] = s;
    __syncthreads();
    float mean = (red[half * 4] + red[half * 4 + 1] + red[half * 4 + 2] + red[half * 4 + 3]) * (1.f / Cn);
    __syncthreads();

    float d0 = v0 - mean, d1 = v1 - mean, d2 = v2 - mean;
    float sq = d0 * d0 + d1 * d1 + d2 * d2;
    for (int o = 16; o > 0; o >>= 1) sq += __shfl_xor_sync(0xffffffffu, sq, o);
    if ((tid & 31) == 0) red[half * 4 + (tid >> 5)] = sq;
    __syncthreads();
    float var = (red[half * 4] + red[half * 4 + 1] + red[half * 4 + 2] + red[half * 4 + 3]) * (1.f / Cn);
    float inv = rsqrtf(var + EPSn);

    float o0 = g[tid]       * d0 * inv + bb[tid];
    float o1 = g[tid + 128] * d1 * inv + bb[tid + 128];
    float o2 = g[tid + 256] * d2 * inv + bb[tid + 256];
    out[base + tid]       = o0;
    out[base + tid + 128] = o1;
    out[base + tid + 256] = o2;
    if (out16) {
        out16[base + tid]       = __float2half(o0);
        out16[base + tid + 128] = __float2half(o1);
        out16[base + tid + 256] = __float2half(o2);
    }
}

// ---------------- host orchestration ----------------
extern "C" void kernel_launch(void* const* d_in, const int* in_sizes, int n_in,
                              void* d_out, int out_size)
{
    (void)in_sizes; (void)n_in; (void)out_size;
    const float* x    = (const float*)d_in[0];
    const float* q1w  = (const float*)d_in[1];
    const float* q1b  = (const float*)d_in[2];
    const float* k1w  = (const float*)d_in[3];
    const float* k1b  = (const float*)d_in[4];
    const float* v1w  = (const float*)d_in[5];
    const float* v1b  = (const float*)d_in[6];
    const float* p1w  = (const float*)d_in[7];
    const float* p1b  = (const float*)d_in[8];
    const float* ln1g = (const float*)d_in[9];
    const float* ln1b = (const float*)d_in[10];
    const float* q2w  = (const float*)d_in[11];
    const float* q2b  = (const float*)d_in[12];
    const float* k2w  = (const float*)d_in[13];
    const float* k2b  = (const float*)d_in[14];
    const float* v2w  = (const float*)d_in[15];
    const float* v2b  = (const float*)d_in[16];
    const float* p2w  = (const float*)d_in[17];
    const float* p2b  = (const float*)d_in[18];
    const float* ln2g = (const float*)d_in[19];
    const float* ln2b = (const float*)d_in[20];
    const float* f1w  = (const float*)d_in[21];
    const float* f1b  = (const float*)d_in[22];
    const float* f2w  = (const float*)d_in[23];
    const float* f2b  = (const float*)d_in[24];
    const float* ln3g = (const float*)d_in[25];
    const float* ln3b = (const float*)d_in[26];
    float* out = (float*)d_out;

    __half *pwqkv1, *pwqkv2, *pwp1, *pwp2, *pwf1, *pwf2;
    __half *px16, *po16, *pr16, *ph16, *pq16, *pk16, *pv16t;
    float *pbqkv1, *pbqkv2, *pp, *pr1, *pr2;
    cudaGetSymbolAddress((void**)&pwqkv1, g_wqkv1);
    cudaGetSymbolAddress((void**)&pwqkv2, g_wqkv2);
    cudaGetSymbolAddress((void**)&pwp1, g_wp1);
    cudaGetSymbolAddress((void**)&pwp2, g_wp2);
    cudaGetSymbolAddress((void**)&pwf1, g_wf1t);
    cudaGetSymbolAddress((void**)&pwf2, g_wf2t);
    cudaGetSymbolAddress((void**)&px16, g_x16);
    cudaGetSymbolAddress((void**)&po16, g_o16);
    cudaGetSymbolAddress((void**)&pr16, g_r16);
    cudaGetSymbolAddress((void**)&ph16, g_h16);
    cudaGetSymbolAddress((void**)&pq16, g_q16);
    cudaGetSymbolAddress((void**)&pk16, g_k16);
    cudaGetSymbolAddress((void**)&pv16t, g_v16t);
    cudaGetSymbolAddress((void**)&pbqkv1, g_bqkv1);
    cudaGetSymbolAddress((void**)&pbqkv2, g_bqkv2);
    cudaGetSymbolAddress((void**)&pp,  g_p);
    cudaGetSymbolAddress((void**)&pr1, g_r1);
    cudaGetSymbolAddress((void**)&pr2, g_r2);

    prep_all<<<(PTOT + 255) / 256, 256>>>(
        x, px16,
        q1w, k1w, v1w, pwqkv1,
        q2w, k2w, v2w, pwqkv2,
        p1w, pwp1, p2w, pwp2,
        f1w, pwf1, f2w, pwf2,
        q1b, k1b, v1b, pbqkv1,
        q2b, k2b, v2b, pbqkv2);

    auto run_layer = [&](const float* xin_f32, const __half* xin_f16,
                         const __half* wqkv, const float* bqkv, const __half* wp,
                         const float* pb, const float* lng, const float* lnb,
                         float* rout, __half* rout16) {
        gemm_f16<<<dim3(3 * Cn / 128, BTn / 128), 256>>>(
            xin_f16, wqkv, bqkv, nullptr, nullptr, BTn, 3 * Cn, Cn, 2, pq16, pk16, pv16t);
        attn_mma<<<dim3(Tn / 128, Bn * Hn), 256>>>(pq16, pk16, pv16t, po16);
        gemm_f16<<<dim3(Cn / 128, BTn / 128), 256>>>(
            po16, wp, pb, pp, nullptr, BTn, Cn, Cn, 0, nullptr, nullptr, nullptr);
        ln_res_k<<<BTn / 2, 256>>>(xin_f32, pp, lng, lnb, rout, rout16);
    };

    run_layer(x,   px16, pwqkv1, pbqkv1, pwp1, p1b, ln1g, ln1b, pr1, pr16);
    run_layer(pr1, pr16, pwqkv2, pbqkv2, pwp2, p2b, ln2g, ln2b, pr2, pr16);

    gemm_f16<<<dim3(FFn / 128, BTn / 128), 256>>>(
        pr16, pwf1, f1b, nullptr, ph16, BTn, FFn, Cn, 1, nullptr, nullptr, nullptr);
    gemm_f16<<<dim3(Cn / 128, BTn / 128), 256>>>(
        ph16, pwf2, f2b, pp, nullptr, BTn, Cn, FFn, 0, nullptr, nullptr, nullptr);
    ln_res_k<<<BTn / 2, 256>>>(pr2, pp, ln3g, ln3b, out, nullptr);
}